// round 5
// baseline (speedup 1.0000x reference)
#include <cuda_runtime.h>
#include <math.h>

#define PI_F 3.14159265358979323846f

// Fixed problem sizes: B=8, C=64, H=W=64, K=3, PD=576, SD=128, NQ=6, NL=2

__device__ float g_Ur[4096];   // [s][z] : column s of U, amplitude z (real)
__device__ float g_Ui[4096];   // imag
__device__ float g_style[48];  // [8][6] style angles

// ---------------------------------------------------------------------------
// Setup kernel: 256 threads, 4 threads/column, 16 register amps each.
// ---------------------------------------------------------------------------
__global__ void qcnn_setup_kernel(const float* __restrict__ style,
                                  const float* __restrict__ s2d_w,
                                  const float* __restrict__ s2d_b,
                                  const float* __restrict__ qcnn,
                                  const float* __restrict__ meas)
{
    const int tid = threadIdx.x;  // 0..255

    if (tid < 48) {
        int b = tid / 6, j = tid - 6 * b;
        float acc = s2d_b[j];
        const float* sp = style + b * 128;
        const float* wp = s2d_w + j * 128;
        #pragma unroll 8
        for (int k = 0; k < 128; k++) acc += sp[k] * wp[k];
        g_style[tid] = tanhf(acc) * PI_F;
    }

    const int c = tid >> 2;
    const int q = tid & 3;
    const unsigned FULL = 0xffffffffu;

    float ur[16], ui[16];
    #pragma unroll
    for (int zz = 0; zz < 16; zz++) {
        ur[zz] = (c == q * 16 + zz) ? 1.f : 0.f;
        ui[zz] = 0.f;
    }

    for (int l = 0; l < 2; l++) {
        #pragma unroll
        for (int i = 0; i < 6; i++) {
            const int m = 1 << (5 - i);
            float thy = qcnn[((l * 6 + i) * 2 + 0) * 3 + 0];
            float thz = qcnn[((l * 6 + i) * 2 + 1) * 3 + 0];
            float cy, sy; sincosf(0.5f * thy, &sy, &cy);
            if (m < 16) {
                #pragma unroll
                for (int zz = 0; zz < 16; zz++) {
                    if (!(zz & m)) {
                        int z1 = zz | m;
                        float r0 = ur[zz], i0 = ui[zz], r1 = ur[z1], i1 = ui[z1];
                        ur[zz] = cy * r0 - sy * r1;  ui[zz] = cy * i0 - sy * i1;
                        ur[z1] = sy * r0 + cy * r1;  ui[z1] = sy * i0 + cy * i1;
                    }
                }
            } else {
                const int lane = m >> 4;
                const int bitv = (q * 16 & m) ? 1 : 0;
                #pragma unroll
                for (int zz = 0; zz < 16; zz++) {
                    float pr = __shfl_xor_sync(FULL, ur[zz], lane);
                    float pi = __shfl_xor_sync(FULL, ui[zz], lane);
                    if (bitv == 0) {
                        ur[zz] = cy * ur[zz] - sy * pr;
                        ui[zz] = cy * ui[zz] - sy * pi;
                    } else {
                        ur[zz] = sy * pr + cy * ur[zz];
                        ui[zz] = sy * pi + cy * ui[zz];
                    }
                }
            }
            float cz, sz; sincosf(0.5f * thz, &sz, &cz);
            #pragma unroll
            for (int zz = 0; zz < 16; zz++) {
                int z = q * 16 + zz;
                float ph = (z & m) ? sz : -sz;
                float r = ur[zz], im = ui[zz];
                ur[zz] = cz * r - ph * im;
                ui[zz] = cz * im + ph * r;
            }
        }
        #pragma unroll
        for (int i = 0; i < 6; i++) {
            const int mc = 1 << (5 - i);
            const int mt = 1 << (5 - ((i + 1) % 6));
            if (mt < 16) {
                #pragma unroll
                for (int zz = 0; zz < 16; zz++) {
                    int z = q * 16 + zz;
                    if ((z & mc) && !(zz & mt)) {
                        int z2 = zz | mt;
                        float tr = ur[zz], ti = ui[zz];
                        ur[zz] = ur[z2];  ui[zz] = ui[z2];
                        ur[z2] = tr;      ui[z2] = ti;
                    }
                }
            } else {
                const int lane = mt >> 4;
                #pragma unroll
                for (int zz = 0; zz < 16; zz++) {
                    float pr = __shfl_xor_sync(FULL, ur[zz], lane);
                    float pi = __shfl_xor_sync(FULL, ui[zz], lane);
                    int z = q * 16 + zz;
                    if (z & mc) { ur[zz] = pr; ui[zz] = pi; }
                }
            }
        }
    }

    #pragma unroll
    for (int i = 0; i < 6; i++) {
        const int m = 1 << (5 - i);
        float th = meas[i * 3 + 0], ph = meas[i * 3 + 1], la = meas[i * 3 + 2];
        float ct, st; sincosf(0.5f * th, &st, &ct);
        float cl, sl; sincosf(la, &sl, &cl);
        float cp, sp; sincosf(ph, &sp, &cp);
        float cpl, spl; sincosf(ph + la, &spl, &cpl);
        float u01r = -cl * st, u01i = -sl * st;
        float u10r =  cp * st, u10i =  sp * st;
        float u11r = cpl * ct, u11i = spl * ct;
        if (m < 16) {
            #pragma unroll
            for (int zz = 0; zz < 16; zz++) {
                if (!(zz & m)) {
                    int z1 = zz | m;
                    float r0 = ur[zz], i0 = ui[zz], r1 = ur[z1], i1 = ui[z1];
                    ur[zz] = ct * r0 + u01r * r1 - u01i * i1;
                    ui[zz] = ct * i0 + u01r * i1 + u01i * r1;
                    ur[z1] = u10r * r0 - u10i * i0 + u11r * r1 - u11i * i1;
                    ui[z1] = u10r * i0 + u10i * r0 + u11r * i1 + u11i * r1;
                }
            }
        } else {
            const int lane = m >> 4;
            const int bitv = (q * 16 & m) ? 1 : 0;
            #pragma unroll
            for (int zz = 0; zz < 16; zz++) {
                float pr = __shfl_xor_sync(FULL, ur[zz], lane);
                float pi = __shfl_xor_sync(FULL, ui[zz], lane);
                float r0 = ur[zz], i0 = ui[zz];
                if (bitv == 0) {
                    ur[zz] = ct * r0 + u01r * pr - u01i * pi;
                    ui[zz] = ct * i0 + u01r * pi + u01i * pr;
                } else {
                    ur[zz] = u10r * pr - u10i * pi + u11r * r0 - u11i * i0;
                    ui[zz] = u10r * pi + u10i * pr + u11r * i0 + u11i * r0;
                }
            }
        }
    }

    #pragma unroll
    for (int zz = 0; zz < 16; zz++) {
        g_Ur[c * 64 + q * 16 + zz] = ur[zz];
        g_Ui[c * 64 + q * 16 + zz] = ui[zz];
    }
}

// ---------------------------------------------------------------------------
// Main fused kernel. 256 blocks x 640 threads, 2 CTAs/SM (regs<=48).
// Block = (batch b, 2 image rows h0, h0+1).
// Phase A: 3x3 conv 64->80 padded channels; weights staged in 2 K-chunks of
//          288 rows (92KB buffer reused). acc[2 rows][4 f32x2] = 16 regs.
// Phase B: quantum part (128 px/block) in two 8-z half-passes (16 acc regs).
// Shared memory (floats), overlaid:
//   conv: Wc[288][80]=23040, inbuf[4][16][66]=4224          (27264)
//   B:    conv_s[2][70][66]=9240, Ur/Ui 8192, a_s[128][65]=8320,
//         e_s[128][9]=1152, params 528                       (27432)
// SMEM = 27432 floats = 109728 B; 2 CTAs = 219456 <= 228KB/SM.
// ---------------------------------------------------------------------------
#define SMEM_FLOATS 27432
#define SMEM_BYTES  (SMEM_FLOATS * 4)

#define FMA2(acc, a, b) asm("fma.rn.f32x2 %0, %1, %2, %0;" : "+l"(acc) : "l"(a), "l"(b))
#define DUP2(d, f)      asm("mov.b64 %0, {%1, %1};" : "=l"(d) : "r"(__float_as_uint(f)))

__global__ __launch_bounds__(640, 2)
void qcnn_main_kernel(const float* __restrict__ x,
                      const float* __restrict__ dat_w,
                      const float* __restrict__ dat_b,
                      const float* __restrict__ out_w,
                      const float* __restrict__ out_b,
                      const float* __restrict__ res_w,
                      const float* __restrict__ res_b,
                      float* __restrict__ out)
{
    extern __shared__ float sm[];
    float* Wc    = sm;                    // [288][80]
    float* inbuf = sm + 23040;            // [4][16][66]
    // Phase-B overlay
    float* conv_s = sm;                   // [2][70][66] = 9240
    float* Urs    = sm + 9240;            // [64][64]
    float* Uis    = Urs + 4096;
    float* a_s    = Uis + 4096;           // [128][65] = 8320
    float* e_s    = a_s + 8320;           // [128][9]  = 1152
    float* pw     = e_s + 1152;           // out_w [384]
    float* pob    = pw + 384;             // out_b [64]
    float* prb    = pob + 64;             // res_b [64]
    float* pst    = prb + 64;             // style[6] @0, dat_b[6] @8

    const int tid = threadIdx.x;
    const int b   = blockIdx.x >> 5;
    const int h0  = (blockIdx.x & 31) << 1;
    const int w   = tid & 63;
    const int cg8 = (tid >> 6) * 8;       // 8-channel group base (0..72)

    unsigned long long acc[2][4];
    #pragma unroll
    for (int o = 0; o < 2; o++)
        #pragma unroll
        for (int j = 0; j < 4; j++) acc[o][j] = 0ULL;

    // --- Phase A: two 32-cin K-chunks; within each, two 16-cin quarters ---
    for (int kc = 0; kc < 2; kc++) {
        __syncthreads();  // prior chunk's readers done
        // stage weights chunk: k = kc*288 + kk, Wc[kk][c]
        const int k0 = kc * 288;
        for (int idx = tid; idx < 70 * 288; idx += 640) {
            int c  = idx / 288;
            int kk = idx - c * 288;
            int k  = k0 + kk;
            float v = (c < 64) ? res_w[c * 576 + k] : dat_w[(c - 64) * 576 + k];
            Wc[kk * 80 + c] = v;
        }
        for (int idx = tid; idx < 288 * 10; idx += 640) {
            int kk = idx / 10;
            Wc[kk * 80 + 70 + (idx - kk * 10)] = 0.f;
        }

        for (int j = 0; j < 2; j++) {
            const int cin0 = kc * 32 + j * 16;
            if (j == 1) __syncthreads();  // j0 readers done before restage
            // stage inbuf: 4 rows x 16 cin x 66
            for (int idx = tid; idx < 4224; idx += 640) {
                int r   = idx / 1056;
                int rem = idx - r * 1056;
                int ci  = rem / 66;
                int ww  = rem - ci * 66;
                int hh  = h0 + r - 1;
                int gw  = ww - 1;
                float v = 0.f;
                if (hh >= 0 && hh < 64 && gw >= 0 && gw < 64)
                    v = x[((b * 64 + cin0 + ci) * 64 + hh) * 64 + gw];
                inbuf[idx] = v;
            }
            __syncthreads();

            const float* ib    = inbuf + w;
            const float* wbase = Wc + (j * 16) * 9 * 80 + cg8;
            #pragma unroll 2
            for (int ci = 0; ci < 16; ci++) {
                #pragma unroll
                for (int dx = 0; dx < 3; dx++) {
                    unsigned long long iv2[4];
                    #pragma unroll
                    for (int r = 0; r < 4; r++) {
                        float iv = ib[(r * 16 + ci) * 66 + dx];
                        DUP2(iv2[r], iv);
                    }
                    #pragma unroll
                    for (int dy = 0; dy < 3; dy++) {
                        const ulonglong2* wp = reinterpret_cast<const ulonglong2*>(
                            wbase + (ci * 9 + dy * 3 + dx) * 80);
                        ulonglong2 wv0 = wp[0];
                        ulonglong2 wv1 = wp[1];
                        #pragma unroll
                        for (int o = 0; o < 2; o++) {
                            FMA2(acc[o][0], wv0.x, iv2[dy + o]);
                            FMA2(acc[o][1], wv0.y, iv2[dy + o]);
                            FMA2(acc[o][2], wv1.x, iv2[dy + o]);
                            FMA2(acc[o][3], wv1.y, iv2[dy + o]);
                        }
                    }
                }
            }
        }
    }
    __syncthreads();  // all Wc/inbuf readers done -> safe to overlay

    // --- Dump conv results; stage U + params ---
    #pragma unroll
    for (int o = 0; o < 2; o++) {
        #pragma unroll
        for (int jj = 0; jj < 4; jj++) {
            int c0 = cg8 + 2 * jj;
            unsigned int lo = (unsigned int)(acc[o][jj] & 0xffffffffULL);
            unsigned int hi = (unsigned int)(acc[o][jj] >> 32);
            if (c0 < 70)     conv_s[(o * 70 + c0) * 66 + w]     = __uint_as_float(lo);
            if (c0 + 1 < 70) conv_s[(o * 70 + c0 + 1) * 66 + w] = __uint_as_float(hi);
        }
    }
    for (int idx = tid; idx < 4096; idx += 640) {
        Urs[idx] = g_Ur[idx];
        Uis[idx] = g_Ui[idx];
    }
    if (tid < 384) pw[tid] = out_w[tid];
    if (tid >= 384 && tid < 448) { pob[tid - 384] = out_b[tid - 384]; prb[tid - 384] = res_b[tid - 384]; }
    if (tid >= 448 && tid < 454) { pst[tid - 448] = g_style[b * 6 + (tid - 448)]; pst[8 + tid - 448] = dat_b[tid - 448]; }
    __syncthreads();

    // --- Phase B: 512 threads = 128 pixels x 4 quarters ---
    if (tid < 512) {
        const int q  = tid & 3;
        const int p2 = tid >> 2;          // pixel 0..127
        const int o  = p2 >> 6;
        const int wq = p2 & 63;

        float cc[6], sn[6];
        #pragma unroll
        for (int i = 0; i < 6; i++) {
            float pre = conv_s[(o * 70 + 64 + i) * 66 + wq];
            float th = tanhf(pre + pst[8 + i]) * PI_F + pst[i];
            sincosf(0.5f * th, &sn[i], &cc[i]);
        }
        #pragma unroll
        for (int zz = 0; zz < 16; zz++) {
            int z = q * 16 + zz;
            float a = ((z >> 5) & 1) ? sn[0] : cc[0];
            #pragma unroll
            for (int i = 1; i < 6; i++) a *= ((z >> (5 - i)) & 1) ? sn[i] : cc[i];
            a_s[p2 * 65 + z] = a;
        }
        __syncwarp();

        // Two half-passes over z = q*16 + half*8 + t (t=0..7). 16 acc regs.
        const float* arow = a_s + p2 * 65;
        float ps[2], sb2[2], sb1[2], sb0[2];
        #pragma unroll
        for (int half = 0; half < 2; half++) {
            unsigned long long prx[4], pix[4];
            #pragma unroll
            for (int k = 0; k < 4; k++) { prx[k] = 0ULL; pix[k] = 0ULL; }
            const float* ub = Urs + q * 16 + half * 8;
            const float* vb = Uis + q * 16 + half * 8;
            #pragma unroll 8
            for (int s = 0; s < 64; s++) {
                float av = arow[s];
                unsigned long long av2;
                DUP2(av2, av);
                ulonglong2 uu = *reinterpret_cast<const ulonglong2*>(ub + s * 64);
                ulonglong2 u2 = *reinterpret_cast<const ulonglong2*>(ub + s * 64 + 4);
                ulonglong2 vv = *reinterpret_cast<const ulonglong2*>(vb + s * 64);
                ulonglong2 v2 = *reinterpret_cast<const ulonglong2*>(vb + s * 64 + 4);
                FMA2(prx[0], uu.x, av2);
                FMA2(prx[1], uu.y, av2);
                FMA2(prx[2], u2.x, av2);
                FMA2(prx[3], u2.y, av2);
                FMA2(pix[0], vv.x, av2);
                FMA2(pix[1], vv.y, av2);
                FMA2(pix[2], v2.x, av2);
                FMA2(pix[3], v2.y, av2);
            }
            float h_ps = 0.f, h_b2 = 0.f, h_b1 = 0.f, h_b0 = 0.f;
            #pragma unroll
            for (int k = 0; k < 4; k++) {   // t = 2k, 2k+1
                unsigned int rlo, rhi, ilo, ihi;
                asm("mov.b64 {%0,%1}, %2;" : "=r"(rlo), "=r"(rhi) : "l"(prx[k]));
                asm("mov.b64 {%0,%1}, %2;" : "=r"(ilo), "=r"(ihi) : "l"(pix[k]));
                float r0 = __uint_as_float(rlo), r1 = __uint_as_float(rhi);
                float i0 = __uint_as_float(ilo), i1 = __uint_as_float(ihi);
                float p0 = r0 * r0 + i0 * i0;
                float p1 = r1 * r1 + i1 * i1;
                float pp = p0 + p1;
                h_ps += pp;
                h_b2 += (k & 2) ? -pp : pp;   // bit2 of t
                h_b1 += (k & 1) ? -pp : pp;   // bit1 of t
                h_b0 += p0 - p1;              // bit0 of t
            }
            ps[half] = h_ps; sb2[half] = h_b2; sb1[half] = h_b1; sb0[half] = h_b0;
        }
        float e[6];
        float pt = ps[0] + ps[1];
        e[0] = (q & 2) ? -pt : pt;            // bit5 = q>>1
        e[1] = (q & 1) ? -pt : pt;            // bit4 = q&1
        e[2] = ps[0] - ps[1];                 // bit3 = half
        e[3] = sb2[0] + sb2[1];               // bit2
        e[4] = sb1[0] + sb1[1];               // bit1
        e[5] = sb0[0] + sb0[1];               // bit0
        #pragma unroll
        for (int i = 0; i < 6; i++) {
            e[i] += __shfl_xor_sync(0xffffffffu, e[i], 1);
            e[i] += __shfl_xor_sync(0xffffffffu, e[i], 2);
        }
        if (q == 0) {
            #pragma unroll
            for (int i = 0; i < 6; i++) e_s[p2 * 9 + i] = e[i];
        }
    }
    __syncthreads();

    // --- Epilogue: 512 threads = (pixel w, 8-ch group), 2 rows each ---
    if (tid < 512) {
        const int wE  = tid & 63;
        const int cgE = tid >> 6;     // 0..7
        #pragma unroll
        for (int o = 0; o < 2; o++) {
            float ev[6];
            #pragma unroll
            for (int i = 0; i < 6; i++) ev[i] = e_s[(o * 64 + wE) * 9 + i];
            #pragma unroll
            for (int j = 0; j < 8; j++) {
                int c = cgE * 8 + j;
                float v = conv_s[(o * 70 + c) * 66 + wE] + pob[c] + prb[c];
                #pragma unroll
                for (int i = 0; i < 6; i++) v += pw[c * 6 + i] * ev[i];
                out[((b * 64 + c) * 64 + (h0 + o)) * 64 + wE] = v;
            }
        }
    }
}

// ---------------------------------------------------------------------------
extern "C" void kernel_launch(void* const* d_in, const int* in_sizes, int n_in,
                              void* d_out, int out_size)
{
    (void)in_sizes; (void)n_in; (void)out_size;
    const float* x      = (const float*)d_in[0];
    const float* style  = (const float*)d_in[1];
    const float* dat_w  = (const float*)d_in[2];
    const float* dat_b  = (const float*)d_in[3];
    const float* s2d_w  = (const float*)d_in[4];
    const float* s2d_b  = (const float*)d_in[5];
    const float* qcnn   = (const float*)d_in[6];
    const float* meas   = (const float*)d_in[7];
    const float* out_w  = (const float*)d_in[8];
    const float* out_b  = (const float*)d_in[9];
    const float* res_w  = (const float*)d_in[10];
    const float* res_b  = (const float*)d_in[11];
    float* out = (float*)d_out;

    cudaFuncSetAttribute(qcnn_main_kernel,
                         cudaFuncAttributeMaxDynamicSharedMemorySize, SMEM_BYTES);

    qcnn_setup_kernel<<<1, 256>>>(style, s2d_w, s2d_b, qcnn, meas);
    qcnn_main_kernel<<<256, 640, SMEM_BYTES>>>(x, dat_w, dat_b, out_w, out_b,
                                               res_w, res_b, out);
}

// round 7
// speedup vs baseline: 1.4072x; 1.4072x over previous
#include <cuda_runtime.h>
#include <cuda_bf16.h>
#include <math.h>
#include <stdint.h>

#define PI_F 3.14159265358979323846f
// B=8, C=64, H=W=64, K=3, PD=576, SD=128, NQ=6, NL=2

__device__ float g_Ur[4096];
__device__ float g_Ui[4096];
__device__ float g_style[48];
// Pre-swizzled B tiles: [9 shifts][hi 80x64 | lo 80x64] bf16, [n][k] rows,
// 16B chunk index ^= (n&7). 20480 B per shift.
__device__ __align__(16) unsigned short g_Bt[9][10240];

__device__ __forceinline__ uint32_t smem_u32(const void* p) {
    uint32_t a;
    asm("{ .reg .u64 t; cvta.to.shared.u64 t, %1; cvt.u32.u64 %0, t; }" : "=r"(a) : "l"(p));
    return a;
}

#define LDSM4(r, a) asm volatile("ldmatrix.sync.aligned.m8n8.x4.shared.b16 {%0,%1,%2,%3}, [%4];" \
    : "=r"((r)[0]), "=r"((r)[1]), "=r"((r)[2]), "=r"((r)[3]) : "r"(a))
#define LDSM2(r, a) asm volatile("ldmatrix.sync.aligned.m8n8.x2.shared.b16 {%0,%1}, [%2];" \
    : "=r"((r)[0]), "=r"((r)[1]) : "r"(a))
#define MMA(d, a, bb2) asm volatile( \
    "mma.sync.aligned.m16n8k16.row.col.f32.bf16.bf16.f32 " \
    "{%0,%1,%2,%3}, {%4,%5,%6,%7}, {%8,%9}, {%0,%1,%2,%3};" \
    : "+f"((d)[0]), "+f"((d)[1]), "+f"((d)[2]), "+f"((d)[3]) \
    : "r"((a)[0]), "r"((a)[1]), "r"((a)[2]), "r"((a)[3]), "r"((bb2)[0]), "r"((bb2)[1]))
#define FMA2(acc, a, b) asm("fma.rn.f32x2 %0, %1, %2, %0;" : "+l"(acc) : "l"(a), "l"(b))
#define DUP2(d, f)      asm("mov.b64 %0, {%1, %1};" : "=l"(d) : "r"(__float_as_uint(f)))

// ---------------------------------------------------------------------------
// Setup kernel: U (64x64 unitary), style angles, pre-swizzled B tiles.
// ---------------------------------------------------------------------------
__global__ void qcnn_setup_kernel(const float* __restrict__ style,
                                  const float* __restrict__ s2d_w,
                                  const float* __restrict__ s2d_b,
                                  const float* __restrict__ qcnn,
                                  const float* __restrict__ meas,
                                  const float* __restrict__ res_w,
                                  const float* __restrict__ dat_w)
{
    const int tid = threadIdx.x;  // 0..255

    if (tid < 48) {
        int b = tid / 6, j = tid - 6 * b;
        float acc = s2d_b[j];
        const float* sp = style + b * 128;
        const float* wp = s2d_w + j * 128;
        #pragma unroll 8
        for (int k = 0; k < 128; k++) acc += sp[k] * wp[k];
        g_style[tid] = tanhf(acc) * PI_F;
    }

    // B tiles: [n][k] rows of 64 bf16 (128B), chunk swizzle ^(n&7), hi+lo
    for (int idx = tid; idx < 46080; idx += 256) {
        int shift = idx / 5120;
        int rem = idx - shift * 5120;
        int n = rem >> 6, c = rem & 63;
        int dy = shift / 3, dx = shift - dy * 3;
        int k = c * 9 + dy * 3 + dx;
        float wv = 0.f;
        if (n < 64) wv = res_w[n * 576 + k];
        else if (n < 70) wv = dat_w[(n - 64) * 576 + k];
        __nv_bfloat16 hi = __float2bfloat16(wv);
        __nv_bfloat16 lo = __float2bfloat16(wv - __bfloat162float(hi));
        int us = (n << 6) + (((c >> 3) ^ (n & 7)) << 3) + (c & 7);
        ((__nv_bfloat16*)g_Bt[shift])[us] = hi;
        ((__nv_bfloat16*)g_Bt[shift])[us + 5120] = lo;
    }

    const int c = tid >> 2;
    const int q = tid & 3;
    const unsigned FULL = 0xffffffffu;
    float ur[16], ui[16];
    #pragma unroll
    for (int zz = 0; zz < 16; zz++) { ur[zz] = (c == q * 16 + zz) ? 1.f : 0.f; ui[zz] = 0.f; }

    for (int l = 0; l < 2; l++) {
        #pragma unroll
        for (int i = 0; i < 6; i++) {
            const int m = 1 << (5 - i);
            float thy = qcnn[((l * 6 + i) * 2 + 0) * 3 + 0];
            float thz = qcnn[((l * 6 + i) * 2 + 1) * 3 + 0];
            float cy, sy; sincosf(0.5f * thy, &sy, &cy);
            if (m < 16) {
                #pragma unroll
                for (int zz = 0; zz < 16; zz++) {
                    if (!(zz & m)) {
                        int z1 = zz | m;
                        float r0 = ur[zz], i0 = ui[zz], r1 = ur[z1], i1 = ui[z1];
                        ur[zz] = cy * r0 - sy * r1;  ui[zz] = cy * i0 - sy * i1;
                        ur[z1] = sy * r0 + cy * r1;  ui[z1] = sy * i0 + cy * i1;
                    }
                }
            } else {
                const int lane = m >> 4;
                const int bitv = (q * 16 & m) ? 1 : 0;
                #pragma unroll
                for (int zz = 0; zz < 16; zz++) {
                    float pr = __shfl_xor_sync(FULL, ur[zz], lane);
                    float pi = __shfl_xor_sync(FULL, ui[zz], lane);
                    if (bitv == 0) { ur[zz] = cy * ur[zz] - sy * pr; ui[zz] = cy * ui[zz] - sy * pi; }
                    else           { ur[zz] = sy * pr + cy * ur[zz]; ui[zz] = sy * pi + cy * ui[zz]; }
                }
            }
            float cz, sz; sincosf(0.5f * thz, &sz, &cz);
            #pragma unroll
            for (int zz = 0; zz < 16; zz++) {
                int z = q * 16 + zz;
                float ph = (z & m) ? sz : -sz;
                float r = ur[zz], im = ui[zz];
                ur[zz] = cz * r - ph * im;
                ui[zz] = cz * im + ph * r;
            }
        }
        #pragma unroll
        for (int i = 0; i < 6; i++) {
            const int mc = 1 << (5 - i);
            const int mt = 1 << (5 - ((i + 1) % 6));
            if (mt < 16) {
                #pragma unroll
                for (int zz = 0; zz < 16; zz++) {
                    int z = q * 16 + zz;
                    if ((z & mc) && !(zz & mt)) {
                        int z2 = zz | mt;
                        float tr = ur[zz], ti = ui[zz];
                        ur[zz] = ur[z2];  ui[zz] = ui[z2];
                        ur[z2] = tr;      ui[z2] = ti;
                    }
                }
            } else {
                const int lane = mt >> 4;
                #pragma unroll
                for (int zz = 0; zz < 16; zz++) {
                    float pr = __shfl_xor_sync(FULL, ur[zz], lane);
                    float pi = __shfl_xor_sync(FULL, ui[zz], lane);
                    int z = q * 16 + zz;
                    if (z & mc) { ur[zz] = pr; ui[zz] = pi; }
                }
            }
        }
    }
    #pragma unroll
    for (int i = 0; i < 6; i++) {
        const int m = 1 << (5 - i);
        float th = meas[i * 3 + 0], ph = meas[i * 3 + 1], la = meas[i * 3 + 2];
        float ct, st; sincosf(0.5f * th, &st, &ct);
        float cl, sl; sincosf(la, &sl, &cl);
        float cp, sp; sincosf(ph, &sp, &cp);
        float cpl, spl; sincosf(ph + la, &spl, &cpl);
        float u01r = -cl * st, u01i = -sl * st;
        float u10r =  cp * st, u10i =  sp * st;
        float u11r = cpl * ct, u11i = spl * ct;
        if (m < 16) {
            #pragma unroll
            for (int zz = 0; zz < 16; zz++) {
                if (!(zz & m)) {
                    int z1 = zz | m;
                    float r0 = ur[zz], i0 = ui[zz], r1 = ur[z1], i1 = ui[z1];
                    ur[zz] = ct * r0 + u01r * r1 - u01i * i1;
                    ui[zz] = ct * i0 + u01r * i1 + u01i * r1;
                    ur[z1] = u10r * r0 - u10i * i0 + u11r * r1 - u11i * i1;
                    ui[z1] = u10r * i0 + u10i * r0 + u11r * i1 + u11i * r1;
                }
            }
        } else {
            const int lane = m >> 4;
            const int bitv = (q * 16 & m) ? 1 : 0;
            #pragma unroll
            for (int zz = 0; zz < 16; zz++) {
                float pr = __shfl_xor_sync(FULL, ur[zz], lane);
                float pi = __shfl_xor_sync(FULL, ui[zz], lane);
                float r0 = ur[zz], i0 = ui[zz];
                if (bitv == 0) {
                    ur[zz] = ct * r0 + u01r * pr - u01i * pi;
                    ui[zz] = ct * i0 + u01r * pi + u01i * pr;
                } else {
                    ur[zz] = u10r * pr - u10i * pi + u11r * r0 - u11i * i0;
                    ui[zz] = u10r * pi + u10i * pr + u11r * i0 + u11i * r0;
                }
            }
        }
    }
    #pragma unroll
    for (int zz = 0; zz < 16; zz++) {
        g_Ur[c * 64 + q * 16 + zz] = ur[zz];
        g_Ui[c * 64 + q * 16 + zz] = ui[zz];
    }
}

// ---------------------------------------------------------------------------
// Main kernel: 128 blocks x 640 threads (single wave). Block = (b, 4 rows).
// Conv via warp-level mma.sync m16n8k16 bf16 (3-term split), 16 compute warps
// each owning M32 x N40 of C[256px][80]; warps 16-19 prefetch B / stage U.
// SMEM (bytes): XPH@0(50688) XPL@50688 Bbuf0@101376(20480) Bbuf1@121856
//   Urs@142336(16384) Uis@158720 e_s@175104(9216) pw@184320 pob@185856
//   prb@186112 pst@186368 | overlays (post-GEMM): conv_s@0 [4][64][80]f32
//   (81920), a_s@81920 [128][65]f32 (33280)
// ---------------------------------------------------------------------------
#define OFF_XPL  50688
#define OFF_B0   101376
#define OFF_URS  142336
#define OFF_UIS  158720
#define OFF_ES   175104
#define OFF_PW   184320
#define OFF_POB  185856
#define OFF_PRB  186112
#define OFF_PST  186368
#define SMEM_BYTES 186432

__global__ __launch_bounds__(640, 1)
void qcnn_main_kernel(const float* __restrict__ x,
                      const float* __restrict__ dat_b,
                      const float* __restrict__ out_w,
                      const float* __restrict__ out_b,
                      const float* __restrict__ res_b,
                      float* __restrict__ out)
{
    extern __shared__ char smc[];
    const uint32_t smem_base = smem_u32(smc);
    __nv_bfloat16* XPH = (__nv_bfloat16*)smc;
    __nv_bfloat16* XPL = (__nv_bfloat16*)(smc + OFF_XPL);
    float* conv_s = (float*)smc;                 // overlay post-GEMM
    float* a_s    = (float*)(smc + 81920);       // overlay post-GEMM
    float* Urs    = (float*)(smc + OFF_URS);
    float* Uis    = (float*)(smc + OFF_UIS);
    float* e_s    = (float*)(smc + OFF_ES);
    float* pw     = (float*)(smc + OFF_PW);
    float* pob    = (float*)(smc + OFF_POB);
    float* prb    = (float*)(smc + OFF_PRB);
    float* pst    = (float*)(smc + OFF_PST);

    const int tid  = threadIdx.x;
    const int wid  = tid >> 5;
    const int lane = tid & 31;
    const int b    = blockIdx.x >> 4;
    const int h0   = (blockIdx.x & 15) << 2;

    // --- stage input hi/lo planes: [r(6)][wpad(66)] rows of 64 bf16 (128B),
    //     16B chunk index ^= (w&7)
    for (int idx = tid; idx < 6144; idx += 640) {
        int r  = idx >> 10;
        int cc = (idx >> 4) & 63;
        int g  = idx & 15;
        int hr = h0 + r - 1;
        float4 v = make_float4(0.f, 0.f, 0.f, 0.f);
        if (hr >= 0 && hr < 64)
            v = *(const float4*)(x + (((b * 64 + cc) * 64 + hr) << 6) + g * 4);
        float vv[4] = {v.x, v.y, v.z, v.w};
        #pragma unroll
        for (int j = 0; j < 4; j++) {
            int w = g * 4 + 1 + j;
            __nv_bfloat16 hi = __float2bfloat16(vv[j]);
            __nv_bfloat16 lo = __float2bfloat16(vv[j] - __bfloat162float(hi));
            int us = ((r * 66 + w) << 6) + (((cc >> 3) ^ (w & 7)) << 3) + (cc & 7);
            XPH[us] = hi;
            XPL[us] = lo;
        }
    }
    for (int idx = tid; idx < 768; idx += 640) {   // pads w=0, w=65
        int r = idx / 128;
        int rem = idx - r * 128;
        int cc = rem >> 1;
        int w = (rem & 1) ? 65 : 0;
        int us = ((r * 66 + w) << 6) + (((cc >> 3) ^ (w & 7)) << 3) + (cc & 7);
        XPH[us] = __float2bfloat16(0.f);
        XPL[us] = __float2bfloat16(0.f);
    }
    // --- B shift 0 into buf 0 ---
    {
        const uint4* src = (const uint4*)(g_Bt[0]);
        uint4* dst = (uint4*)(smc + OFF_B0);
        for (int i = tid; i < 1280; i += 640) dst[i] = src[i];
    }

    // compute-warp geometry
    const int mt  = wid >> 1;            // M32 tile 0..7 (wid<16)
    const int nh  = wid & 1;
    const int o   = mt >> 1;
    const int w0c = (mt & 1) * 32;
    const int n0  = nh * 40;
    const int l15 = lane & 15;
    const int bln = lane & 7;
    const uint32_t brow = (uint32_t)(n0 + bln) * 128;

    float acc[2][5][4];
    #pragma unroll
    for (int m = 0; m < 2; m++)
        #pragma unroll
        for (int nt = 0; nt < 5; nt++)
            #pragma unroll
            for (int j = 0; j < 4; j++) acc[m][nt][j] = 0.f;

    for (int st = 0; st < 9; st++) {
        __syncthreads();
        const uint32_t bb = smem_base + OFF_B0 + (uint32_t)(st & 1) * 20480;
        if (wid < 16) {
            const int dy = st / 3, dx = st - dy * 3;
            const int srow = o + dy;
            const int ws0 = w0c + l15 + dx;
            const int ws1 = ws0 + 16;
            const uint32_t arow0 = (uint32_t)((srow * 66 + ws0) << 7);
            const uint32_t arow1 = (uint32_t)((srow * 66 + ws1) << 7);
            const uint32_t sw0 = ws0 & 7, sw1 = ws1 & 7;
            const uint32_t xb = smem_base;
            #pragma unroll
            for (int k0 = 0; k0 < 64; k0 += 16) {
                const uint32_t kca = (uint32_t)(k0 >> 3) + (uint32_t)(lane >> 4);
                uint32_t ah0[4], ah1[4], al0[4], al1[4], bf[5][2];
                uint32_t ad0 = xb + arow0 + ((kca ^ sw0) << 4);
                uint32_t ad1 = xb + arow1 + ((kca ^ sw1) << 4);
                LDSM4(ah0, ad0);
                LDSM4(ah1, ad1);
                LDSM4(al0, ad0 + OFF_XPL);
                LDSM4(al1, ad1 + OFF_XPL);
                const uint32_t kcb = (uint32_t)(k0 >> 3) + (uint32_t)((lane >> 3) & 1);
                const uint32_t boff = bb + brow + ((kcb ^ (uint32_t)bln) << 4);
                #pragma unroll
                for (int nt = 0; nt < 5; nt++) LDSM2(bf[nt], boff + nt * 1024);
                #pragma unroll
                for (int nt = 0; nt < 5; nt++) { MMA(acc[0][nt], ah0, bf[nt]); MMA(acc[1][nt], ah1, bf[nt]); }
                #pragma unroll
                for (int nt = 0; nt < 5; nt++) { MMA(acc[0][nt], al0, bf[nt]); MMA(acc[1][nt], al1, bf[nt]); }
                #pragma unroll
                for (int nt = 0; nt < 5; nt++) LDSM2(bf[nt], boff + nt * 1024 + 10240);
                #pragma unroll
                for (int nt = 0; nt < 5; nt++) { MMA(acc[0][nt], ah0, bf[nt]); MMA(acc[1][nt], ah1, bf[nt]); }
            }
        } else {
            const int t2 = tid - 512;
            if (st < 8) {   // prefetch next shift's B into other buffer
                const uint4* src = (const uint4*)(g_Bt[st + 1]);
                uint4* dst = (uint4*)(smc + OFF_B0 + ((st + 1) & 1) * 20480);
                #pragma unroll
                for (int i = 0; i < 10; i++) dst[t2 + i * 128] = src[t2 + i * 128];
            }
            if (st == 0) {  // stage U + params (regions disjoint from XP/B)
                for (int i = t2; i < 1024; i += 128) {
                    ((uint4*)Urs)[i] = ((const uint4*)g_Ur)[i];
                    ((uint4*)Uis)[i] = ((const uint4*)g_Ui)[i];
                }
                if (t2 < 96) ((uint4*)pw)[t2] = ((const uint4*)out_w)[t2];
                else if (t2 < 112) ((uint4*)pob)[t2 - 96] = ((const uint4*)out_b)[t2 - 96];
                else if (t2 < 128) ((uint4*)prb)[t2 - 112] = ((const uint4*)res_b)[t2 - 112];
                if (t2 < 6) { pst[t2] = g_style[b * 6 + t2]; pst[8 + t2] = dat_b[t2]; }
            }
        }
    }
    __syncthreads();   // all XP/B readers done -> safe to overlay conv_s

    // --- writeout acc -> conv_s [o][w][80] ---
    if (wid < 16) {
        const int r0 = lane >> 2;
        const int nc = n0 + (lane & 3) * 2;
        #pragma unroll
        for (int m = 0; m < 2; m++) {
            const int wpx = w0c + m * 16 + r0;
            #pragma unroll
            for (int nt = 0; nt < 5; nt++) {
                *(float2*)&conv_s[(o * 64 + wpx) * 80 + nc + nt * 8] =
                    make_float2(acc[m][nt][0], acc[m][nt][1]);
                *(float2*)&conv_s[(o * 64 + wpx + 8) * 80 + nc + nt * 8] =
                    make_float2(acc[m][nt][2], acc[m][nt][3]);
            }
        }
    }
    __syncthreads();

    // --- Phase B: 512 threads = 128 px x 4 quarters, two iterations ---
    if (tid < 512) {
        const int q  = tid & 3;
        const int p2 = tid >> 2;
        #pragma unroll
        for (int it = 0; it < 2; it++) {
            const int p  = it * 128 + p2;
            const int o2 = p >> 6;
            const int wq = p & 63;

            float cc[6], sn[6];
            #pragma unroll
            for (int i = 0; i < 6; i++) {
                float pre = conv_s[(o2 * 64 + wq) * 80 + 64 + i];
                float th = tanhf(pre + pst[8 + i]) * PI_F + pst[i];
                sincosf(0.5f * th, &sn[i], &cc[i]);
            }
            #pragma unroll
            for (int zz = 0; zz < 16; zz++) {
                int z = q * 16 + zz;
                float a = ((z >> 5) & 1) ? sn[0] : cc[0];
                #pragma unroll
                for (int i = 1; i < 6; i++) a *= ((z >> (5 - i)) & 1) ? sn[i] : cc[i];
                a_s[p2 * 65 + z] = a;
            }
            __syncwarp();

            unsigned long long prx[8], pix8[8];
            #pragma unroll
            for (int k = 0; k < 8; k++) { prx[k] = 0ULL; pix8[k] = 0ULL; }
            const float* arow = a_s + p2 * 65;
            #pragma unroll 8
            for (int s = 0; s < 64; s++) {
                float av = arow[s];
                unsigned long long av2;
                DUP2(av2, av);
                const ulonglong2* u2 = (const ulonglong2*)(Urs + s * 64 + q * 16);
                const ulonglong2* v2 = (const ulonglong2*)(Uis + s * 64 + q * 16);
                #pragma unroll
                for (int j = 0; j < 4; j++) {
                    ulonglong2 uu = u2[j];
                    ulonglong2 vv = v2[j];
                    FMA2(prx[2 * j],      uu.x, av2);
                    FMA2(prx[2 * j + 1],  uu.y, av2);
                    FMA2(pix8[2 * j],     vv.x, av2);
                    FMA2(pix8[2 * j + 1], vv.y, av2);
                }
            }
            float psum = 0.f, e2 = 0.f, e3 = 0.f, e4 = 0.f, e5 = 0.f;
            #pragma unroll
            for (int k = 0; k < 8; k++) {
                unsigned int rlo, rhi, ilo, ihi;
                asm("mov.b64 {%0,%1}, %2;" : "=r"(rlo), "=r"(rhi) : "l"(prx[k]));
                asm("mov.b64 {%0,%1}, %2;" : "=r"(ilo), "=r"(ihi) : "l"(pix8[k]));
                float r0 = __uint_as_float(rlo), r1 = __uint_as_float(rhi);
                float i0 = __uint_as_float(ilo), i1 = __uint_as_float(ihi);
                float p0 = r0 * r0 + i0 * i0;
                float p1 = r1 * r1 + i1 * i1;
                const int t0 = 2 * k;
                psum += p0 + p1;
                e2 += ((t0 >> 3) & 1) ? -(p0 + p1) : (p0 + p1);
                e3 += ((t0 >> 2) & 1) ? -(p0 + p1) : (p0 + p1);
                e4 += ((t0 >> 1) & 1) ? -(p0 + p1) : (p0 + p1);
                e5 += p0 - p1;
            }
            float e[6];
            e[0] = (q & 2) ? -psum : psum;
            e[1] = (q & 1) ? -psum : psum;
            e[2] = e2; e[3] = e3; e[4] = e4; e[5] = e5;
            #pragma unroll
            for (int i = 0; i < 6; i++) {
                e[i] += __shfl_xor_sync(0xffffffffu, e[i], 1);
                e[i] += __shfl_xor_sync(0xffffffffu, e[i], 2);
            }
            if (q == 0) {
                #pragma unroll
                for (int i = 0; i < 6; i++) e_s[p * 9 + i] = e[i];
            }
            __syncwarp();
        }
    }
    __syncthreads();

    // --- Epilogue: 512 threads = (pixel, 8-ch group), 4 rows ---
    if (tid < 512) {
        const int wE  = tid & 63;
        const int cgE = tid >> 6;
        #pragma unroll
        for (int o2 = 0; o2 < 4; o2++) {
            float ev[6];
            #pragma unroll
            for (int i = 0; i < 6; i++) ev[i] = e_s[(o2 * 64 + wE) * 9 + i];
            #pragma unroll
            for (int j = 0; j < 8; j++) {
                int c = cgE * 8 + j;
                float v = conv_s[(o2 * 64 + wE) * 80 + c] + pob[c] + prb[c];
                #pragma unroll
                for (int i = 0; i < 6; i++) v += pw[c * 6 + i] * ev[i];
                out[((b * 64 + c) * 64 + (h0 + o2)) * 64 + wE] = v;
            }
        }
    }
}

// ---------------------------------------------------------------------------
extern "C" void kernel_launch(void* const* d_in, const int* in_sizes, int n_in,
                              void* d_out, int out_size)
{
    (void)in_sizes; (void)n_in; (void)out_size;
    const float* x      = (const float*)d_in[0];
    const float* style  = (const float*)d_in[1];
    const float* dat_w  = (const float*)d_in[2];
    const float* dat_b  = (const float*)d_in[3];
    const float* s2d_w  = (const float*)d_in[4];
    const float* s2d_b  = (const float*)d_in[5];
    const float* qcnn   = (const float*)d_in[6];
    const float* meas   = (const float*)d_in[7];
    const float* out_w  = (const float*)d_in[8];
    const float* out_b  = (const float*)d_in[9];
    const float* res_w  = (const float*)d_in[10];
    const float* res_b  = (const float*)d_in[11];
    float* out = (float*)d_out;

    cudaFuncSetAttribute(qcnn_main_kernel,
                         cudaFuncAttributeMaxDynamicSharedMemorySize, SMEM_BYTES);

    qcnn_setup_kernel<<<1, 256>>>(style, s2d_w, s2d_b, qcnn, meas, res_w, dat_w);
    qcnn_main_kernel<<<128, 640, SMEM_BYTES>>>(x, dat_b, out_w, out_b, res_b, out);
}

// round 8
// speedup vs baseline: 3.1946x; 2.2702x over previous
#include <cuda_runtime.h>
#include <cuda_bf16.h>
#include <math.h>
#include <stdint.h>

#define PI_F 3.14159265358979323846f
// B=8, C=64, H=W=64, K=3, PD=576, SD=128, NQ=6, NL=2

__device__ float g_style[48];
// Pre-swizzled B tiles: [9 shifts][hi 80x64 | lo 80x64] bf16, [n][k] rows,
// 16B chunk index ^= (n&7). 20480 B per shift.
__device__ __align__(16) unsigned short g_Bt[9][10240];
// U bf16 planes: [z][s] rows of 64 bf16 (128B), chunk ^= (z&7).
// plane 0 = Ur hi, 1 = Ur lo, 2 = Ui hi, 3 = Ui lo.
__device__ __align__(16) unsigned short g_Ubf[4][4096];

__device__ __forceinline__ uint32_t smem_u32(const void* p) {
    uint32_t a;
    asm("{ .reg .u64 t; cvta.to.shared.u64 t, %1; cvt.u32.u64 %0, t; }" : "=r"(a) : "l"(p));
    return a;
}

#define LDSM4(r, a) asm volatile("ldmatrix.sync.aligned.m8n8.x4.shared.b16 {%0,%1,%2,%3}, [%4];" \
    : "=r"((r)[0]), "=r"((r)[1]), "=r"((r)[2]), "=r"((r)[3]) : "r"(a))
#define LDSM2(r, a) asm volatile("ldmatrix.sync.aligned.m8n8.x2.shared.b16 {%0,%1}, [%2];" \
    : "=r"((r)[0]), "=r"((r)[1]) : "r"(a))
#define MMA(d, a, bb2) asm volatile( \
    "mma.sync.aligned.m16n8k16.row.col.f32.bf16.bf16.f32 " \
    "{%0,%1,%2,%3}, {%4,%5,%6,%7}, {%8,%9}, {%0,%1,%2,%3};" \
    : "+f"((d)[0]), "+f"((d)[1]), "+f"((d)[2]), "+f"((d)[3]) \
    : "r"((a)[0]), "r"((a)[1]), "r"((a)[2]), "r"((a)[3]), "r"((bb2)[0]), "r"((bb2)[1]))

// ---------------------------------------------------------------------------
// Setup kernel 1: B tiles, parallel across 180 blocks.
// ---------------------------------------------------------------------------
__global__ void qcnn_setup_b(const float* __restrict__ res_w,
                             const float* __restrict__ dat_w)
{
    int idx = blockIdx.x * 256 + threadIdx.x;
    if (idx >= 46080) return;
    int shift = idx / 5120;
    int rem = idx - shift * 5120;
    int n = rem >> 6, c = rem & 63;
    int dy = shift / 3, dx = shift - dy * 3;
    int k = c * 9 + dy * 3 + dx;
    float wv = 0.f;
    if (n < 64) wv = res_w[n * 576 + k];
    else if (n < 70) wv = dat_w[(n - 64) * 576 + k];
    __nv_bfloat16 hi = __float2bfloat16(wv);
    __nv_bfloat16 lo = __float2bfloat16(wv - __bfloat162float(hi));
    int us = (n << 6) + (((c >> 3) ^ (n & 7)) << 3) + (c & 7);
    ((__nv_bfloat16*)g_Bt[shift])[us] = hi;
    ((__nv_bfloat16*)g_Bt[shift])[us + 5120] = lo;
}

// ---------------------------------------------------------------------------
// Setup kernel 2: style angles + 64x64 unitary -> bf16 split planes (g_Ubf).
// 256 threads: 4 threads per column (s), 16 register amps each.
// ---------------------------------------------------------------------------
__global__ void qcnn_setup_qc(const float* __restrict__ style,
                              const float* __restrict__ s2d_w,
                              const float* __restrict__ s2d_b,
                              const float* __restrict__ qcnn,
                              const float* __restrict__ meas)
{
    const int tid = threadIdx.x;  // 0..255

    if (tid < 48) {
        int b = tid / 6, j = tid - 6 * b;
        float acc = s2d_b[j];
        const float* sp = style + b * 128;
        const float* wp = s2d_w + j * 128;
        #pragma unroll 8
        for (int k = 0; k < 128; k++) acc += sp[k] * wp[k];
        g_style[tid] = tanhf(acc) * PI_F;
    }

    const int c = tid >> 2;
    const int q = tid & 3;
    const unsigned FULL = 0xffffffffu;
    float ur[16], ui[16];
    #pragma unroll
    for (int zz = 0; zz < 16; zz++) { ur[zz] = (c == q * 16 + zz) ? 1.f : 0.f; ui[zz] = 0.f; }

    for (int l = 0; l < 2; l++) {
        #pragma unroll
        for (int i = 0; i < 6; i++) {
            const int m = 1 << (5 - i);
            float thy = qcnn[((l * 6 + i) * 2 + 0) * 3 + 0];
            float thz = qcnn[((l * 6 + i) * 2 + 1) * 3 + 0];
            float cy, sy; sincosf(0.5f * thy, &sy, &cy);
            if (m < 16) {
                #pragma unroll
                for (int zz = 0; zz < 16; zz++) {
                    if (!(zz & m)) {
                        int z1 = zz | m;
                        float r0 = ur[zz], i0 = ui[zz], r1 = ur[z1], i1 = ui[z1];
                        ur[zz] = cy * r0 - sy * r1;  ui[zz] = cy * i0 - sy * i1;
                        ur[z1] = sy * r0 + cy * r1;  ui[z1] = sy * i0 + cy * i1;
                    }
                }
            } else {
                const int lane = m >> 4;
                const int bitv = (q * 16 & m) ? 1 : 0;
                #pragma unroll
                for (int zz = 0; zz < 16; zz++) {
                    float pr = __shfl_xor_sync(FULL, ur[zz], lane);
                    float pi = __shfl_xor_sync(FULL, ui[zz], lane);
                    if (bitv == 0) { ur[zz] = cy * ur[zz] - sy * pr; ui[zz] = cy * ui[zz] - sy * pi; }
                    else           { ur[zz] = sy * pr + cy * ur[zz]; ui[zz] = sy * pi + cy * ui[zz]; }
                }
            }
            float cz, sz; sincosf(0.5f * thz, &sz, &cz);
            #pragma unroll
            for (int zz = 0; zz < 16; zz++) {
                int z = q * 16 + zz;
                float ph = (z & m) ? sz : -sz;
                float r = ur[zz], im = ui[zz];
                ur[zz] = cz * r - ph * im;
                ui[zz] = cz * im + ph * r;
            }
        }
        #pragma unroll
        for (int i = 0; i < 6; i++) {
            const int mc = 1 << (5 - i);
            const int mt = 1 << (5 - ((i + 1) % 6));
            if (mt < 16) {
                #pragma unroll
                for (int zz = 0; zz < 16; zz++) {
                    int z = q * 16 + zz;
                    if ((z & mc) && !(zz & mt)) {
                        int z2 = zz | mt;
                        float tr = ur[zz], ti = ui[zz];
                        ur[zz] = ur[z2];  ui[zz] = ui[z2];
                        ur[z2] = tr;      ui[z2] = ti;
                    }
                }
            } else {
                const int lane = mt >> 4;
                #pragma unroll
                for (int zz = 0; zz < 16; zz++) {
                    float pr = __shfl_xor_sync(FULL, ur[zz], lane);
                    float pi = __shfl_xor_sync(FULL, ui[zz], lane);
                    int z = q * 16 + zz;
                    if (z & mc) { ur[zz] = pr; ui[zz] = pi; }
                }
            }
        }
    }
    #pragma unroll
    for (int i = 0; i < 6; i++) {
        const int m = 1 << (5 - i);
        float th = meas[i * 3 + 0], ph = meas[i * 3 + 1], la = meas[i * 3 + 2];
        float ct, st; sincosf(0.5f * th, &st, &ct);
        float cl, sl; sincosf(la, &sl, &cl);
        float cp, sp; sincosf(ph, &sp, &cp);
        float cpl, spl; sincosf(ph + la, &spl, &cpl);
        float u01r = -cl * st, u01i = -sl * st;
        float u10r =  cp * st, u10i =  sp * st;
        float u11r = cpl * ct, u11i = spl * ct;
        if (m < 16) {
            #pragma unroll
            for (int zz = 0; zz < 16; zz++) {
                if (!(zz & m)) {
                    int z1 = zz | m;
                    float r0 = ur[zz], i0 = ui[zz], r1 = ur[z1], i1 = ui[z1];
                    ur[zz] = ct * r0 + u01r * r1 - u01i * i1;
                    ui[zz] = ct * i0 + u01r * i1 + u01i * r1;
                    ur[z1] = u10r * r0 - u10i * i0 + u11r * r1 - u11i * i1;
                    ui[z1] = u10r * i0 + u10i * r0 + u11r * i1 + u11i * r1;
                }
            }
        } else {
            const int lane = m >> 4;
            const int bitv = (q * 16 & m) ? 1 : 0;
            #pragma unroll
            for (int zz = 0; zz < 16; zz++) {
                float pr = __shfl_xor_sync(FULL, ur[zz], lane);
                float pi = __shfl_xor_sync(FULL, ui[zz], lane);
                float r0 = ur[zz], i0 = ui[zz];
                if (bitv == 0) {
                    ur[zz] = ct * r0 + u01r * pr - u01i * pi;
                    ui[zz] = ct * i0 + u01r * pi + u01i * pr;
                } else {
                    ur[zz] = u10r * pr - u10i * pi + u11r * r0 - u11i * i0;
                    ui[zz] = u10r * pi + u10i * pr + u11r * i0 + u11i * r0;
                }
            }
        }
    }
    // write bf16 split planes, transposed to [z][s], ldmatrix-swizzled
    #pragma unroll
    for (int zz = 0; zz < 16; zz++) {
        int z = q * 16 + zz;
        int us = (z << 6) + (((c >> 3) ^ (z & 7)) << 3) + (c & 7);
        __nv_bfloat16 rh = __float2bfloat16(ur[zz]);
        __nv_bfloat16 rl = __float2bfloat16(ur[zz] - __bfloat162float(rh));
        __nv_bfloat16 ih = __float2bfloat16(ui[zz]);
        __nv_bfloat16 il = __float2bfloat16(ui[zz] - __bfloat162float(ih));
        ((__nv_bfloat16*)g_Ubf[0])[us] = rh;
        ((__nv_bfloat16*)g_Ubf[1])[us] = rl;
        ((__nv_bfloat16*)g_Ubf[2])[us] = ih;
        ((__nv_bfloat16*)g_Ubf[3])[us] = il;
    }
}

// ---------------------------------------------------------------------------
// Main kernel: 128 blocks x 640 threads (single wave). Block = (b, 4 rows).
// Conv AND quantum matvec on mma.sync m16n8k16 bf16 (3-term split each).
// SMEM (bytes):
//   XPH@0(50688) XPL@50688 | B0@101376(20480) B1@121856(20480)
//   UBF@147456 (4 x 8192 = 32768)  e_s@180224(9216)
//   pw@189440(1536) pob@190976(256) prb@191232(256) pst@191488(64)
// Overlays (post-conv): conv_s@0 [4][64][80]f32 (81920),
//   a_hi@81920(32768), a_lo@114688(32768)  -> ends 147456 (flush vs UBF)
// ---------------------------------------------------------------------------
#define OFF_XPL  50688
#define OFF_B0   101376
#define OFF_AHI  81920
#define OFF_ALO  114688
#define OFF_UBF  147456
#define OFF_ES   180224
#define OFF_PW   189440
#define OFF_POB  190976
#define OFF_PRB  191232
#define OFF_PST  191488
#define SMEM_BYTES 191552

__global__ __launch_bounds__(640, 1)
void qcnn_main_kernel(const float* __restrict__ x,
                      const float* __restrict__ dat_b,
                      const float* __restrict__ out_w,
                      const float* __restrict__ out_b,
                      const float* __restrict__ res_b,
                      float* __restrict__ out)
{
    extern __shared__ char smc[];
    const uint32_t smem_base = smem_u32(smc);
    __nv_bfloat16* XPH = (__nv_bfloat16*)smc;
    __nv_bfloat16* XPL = (__nv_bfloat16*)(smc + OFF_XPL);
    float* conv_s = (float*)smc;                 // overlay post-GEMM
    float* e_s    = (float*)(smc + OFF_ES);
    float* pw     = (float*)(smc + OFF_PW);
    float* pob    = (float*)(smc + OFF_POB);
    float* prb    = (float*)(smc + OFF_PRB);
    float* pst    = (float*)(smc + OFF_PST);

    const int tid  = threadIdx.x;
    const int wid  = tid >> 5;
    const int lane = tid & 31;
    const int b    = blockIdx.x >> 4;
    const int h0   = (blockIdx.x & 15) << 2;

    // --- stage input hi/lo planes: [r(6)][wpad(66)] rows of 64 bf16 (128B),
    //     16B chunk index ^= (w&7)
    for (int idx = tid; idx < 6144; idx += 640) {
        int r  = idx >> 10;
        int cc = (idx >> 4) & 63;
        int g  = idx & 15;
        int hr = h0 + r - 1;
        float4 v = make_float4(0.f, 0.f, 0.f, 0.f);
        if (hr >= 0 && hr < 64)
            v = *(const float4*)(x + (((b * 64 + cc) * 64 + hr) << 6) + g * 4);
        float vv[4] = {v.x, v.y, v.z, v.w};
        #pragma unroll
        for (int j = 0; j < 4; j++) {
            int w = g * 4 + 1 + j;
            __nv_bfloat16 hi = __float2bfloat16(vv[j]);
            __nv_bfloat16 lo = __float2bfloat16(vv[j] - __bfloat162float(hi));
            int us = ((r * 66 + w) << 6) + (((cc >> 3) ^ (w & 7)) << 3) + (cc & 7);
            XPH[us] = hi;
            XPL[us] = lo;
        }
    }
    for (int idx = tid; idx < 768; idx += 640) {   // pads w=0, w=65
        int r = idx / 128;
        int rem = idx - r * 128;
        int cc = rem >> 1;
        int w = (rem & 1) ? 65 : 0;
        int us = ((r * 66 + w) << 6) + (((cc >> 3) ^ (w & 7)) << 3) + (cc & 7);
        XPH[us] = __float2bfloat16(0.f);
        XPL[us] = __float2bfloat16(0.f);
    }
    // --- B shift 0 into buf 0 ---
    {
        const uint4* src = (const uint4*)(g_Bt[0]);
        uint4* dst = (uint4*)(smc + OFF_B0);
        for (int i = tid; i < 1280; i += 640) dst[i] = src[i];
    }

    // compute-warp geometry (conv)
    const int mt  = wid >> 1;
    const int nh  = wid & 1;
    const int o   = mt >> 1;
    const int w0c = (mt & 1) * 32;
    const int n0  = nh * 40;
    const int l15 = lane & 15;
    const int bln = lane & 7;
    const uint32_t brow = (uint32_t)(n0 + bln) * 128;

    float acc[2][5][4];
    #pragma unroll
    for (int m = 0; m < 2; m++)
        #pragma unroll
        for (int nt = 0; nt < 5; nt++)
            #pragma unroll
            for (int j = 0; j < 4; j++) acc[m][nt][j] = 0.f;

    for (int st = 0; st < 9; st++) {
        __syncthreads();
        const uint32_t bb = smem_base + OFF_B0 + (uint32_t)(st & 1) * 20480;
        if (wid < 16) {
            const int dy = st / 3, dx = st - dy * 3;
            const int srow = o + dy;
            const int ws0 = w0c + l15 + dx;
            const int ws1 = ws0 + 16;
            const uint32_t arow0 = (uint32_t)((srow * 66 + ws0) << 7);
            const uint32_t arow1 = (uint32_t)((srow * 66 + ws1) << 7);
            const uint32_t sw0 = ws0 & 7, sw1 = ws1 & 7;
            const uint32_t xb = smem_base;
            #pragma unroll
            for (int k0 = 0; k0 < 64; k0 += 16) {
                const uint32_t kca = (uint32_t)(k0 >> 3) + (uint32_t)(lane >> 4);
                uint32_t ah0[4], ah1[4], al0[4], al1[4], bf[5][2];
                uint32_t ad0 = xb + arow0 + ((kca ^ sw0) << 4);
                uint32_t ad1 = xb + arow1 + ((kca ^ sw1) << 4);
                LDSM4(ah0, ad0);
                LDSM4(ah1, ad1);
                LDSM4(al0, ad0 + OFF_XPL);
                LDSM4(al1, ad1 + OFF_XPL);
                const uint32_t kcb = (uint32_t)(k0 >> 3) + (uint32_t)((lane >> 3) & 1);
                const uint32_t boff = bb + brow + ((kcb ^ (uint32_t)bln) << 4);
                #pragma unroll
                for (int nt = 0; nt < 5; nt++) LDSM2(bf[nt], boff + nt * 1024);
                #pragma unroll
                for (int nt = 0; nt < 5; nt++) { MMA(acc[0][nt], ah0, bf[nt]); MMA(acc[1][nt], ah1, bf[nt]); }
                #pragma unroll
                for (int nt = 0; nt < 5; nt++) { MMA(acc[0][nt], al0, bf[nt]); MMA(acc[1][nt], al1, bf[nt]); }
                #pragma unroll
                for (int nt = 0; nt < 5; nt++) LDSM2(bf[nt], boff + nt * 1024 + 10240);
                #pragma unroll
                for (int nt = 0; nt < 5; nt++) { MMA(acc[0][nt], ah0, bf[nt]); MMA(acc[1][nt], ah1, bf[nt]); }
            }
        } else {
            const int t2 = tid - 512;
            if (st < 8) {
                const uint4* src = (const uint4*)(g_Bt[st + 1]);
                uint4* dst = (uint4*)(smc + OFF_B0 + ((st + 1) & 1) * 20480);
                #pragma unroll
                for (int i = 0; i < 10; i++) dst[t2 + i * 128] = src[t2 + i * 128];
            }
            if (st == 0) {  // stage U planes + params
                for (int i = t2; i < 2048; i += 128)
                    ((uint4*)(smc + OFF_UBF))[i] = ((const uint4*)g_Ubf)[i];
                if (t2 < 96) ((uint4*)pw)[t2] = ((const uint4*)out_w)[t2];
                else if (t2 < 112) ((uint4*)pob)[t2 - 96] = ((const uint4*)out_b)[t2 - 96];
                else if (t2 < 128) ((uint4*)prb)[t2 - 112] = ((const uint4*)res_b)[t2 - 112];
                if (t2 < 6) { pst[t2] = g_style[b * 6 + t2]; pst[8 + t2] = dat_b[t2]; }
            }
        }
    }
    __syncthreads();   // all XP/B readers done -> safe to overlay conv_s

    // --- writeout conv acc -> conv_s [o][w][80] ---
    if (wid < 16) {
        const int r0 = lane >> 2;
        const int nc = n0 + (lane & 3) * 2;
        #pragma unroll
        for (int m = 0; m < 2; m++) {
            const int wpx = w0c + m * 16 + r0;
            #pragma unroll
            for (int nt = 0; nt < 5; nt++) {
                *(float2*)&conv_s[(o * 64 + wpx) * 80 + nc + nt * 8] =
                    make_float2(acc[m][nt][0], acc[m][nt][1]);
                *(float2*)&conv_s[(o * 64 + wpx + 8) * 80 + nc + nt * 8] =
                    make_float2(acc[m][nt][2], acc[m][nt][3]);
            }
        }
    }
    __syncthreads();

    // --- build product-state a as bf16 hi/lo planes [p(256)][s(64)] ---
    if (tid < 512) {
        const int q  = tid & 3;
        const int p2 = tid >> 2;
        #pragma unroll
        for (int it = 0; it < 2; it++) {
            const int p  = it * 128 + p2;
            const int o2 = p >> 6;
            const int wq = p & 63;
            float cc6[6], sn6[6];
            #pragma unroll
            for (int i = 0; i < 6; i++) {
                float pre = conv_s[(o2 * 64 + wq) * 80 + 64 + i];
                float th = tanhf(pre + pst[8 + i]) * PI_F + pst[i];
                sincosf(0.5f * th, &sn6[i], &cc6[i]);
            }
            char* ah = smc + OFF_AHI + (p << 7);
            char* al = smc + OFF_ALO + (p << 7);
            const int psw = p & 7;
            #pragma unroll
            for (int zz = 0; zz < 16; zz += 2) {
                int s = q * 16 + zz;
                float a0 = ((s >> 5) & 1) ? sn6[0] : cc6[0];
                float a1 = (((s + 1) >> 5) & 1) ? sn6[0] : cc6[0];
                #pragma unroll
                for (int i = 1; i < 6; i++) {
                    a0 *= ((s >> (5 - i)) & 1) ? sn6[i] : cc6[i];
                    a1 *= (((s + 1) >> (5 - i)) & 1) ? sn6[i] : cc6[i];
                }
                __nv_bfloat16 h0 = __float2bfloat16(a0);
                __nv_bfloat16 h1 = __float2bfloat16(a1);
                __nv_bfloat16 l0 = __float2bfloat16(a0 - __bfloat162float(h0));
                __nv_bfloat16 l1 = __float2bfloat16(a1 - __bfloat162float(h1));
                uint32_t vh = ((uint32_t)__bfloat16_as_ushort(h1) << 16) | __bfloat16_as_ushort(h0);
                uint32_t vl = ((uint32_t)__bfloat16_as_ushort(l1) << 16) | __bfloat16_as_ushort(l0);
                int off = ((((s >> 3)) ^ psw) << 4) + ((s & 7) << 1);
                *(uint32_t*)(ah + off) = vh;
                *(uint32_t*)(al + off) = vl;
            }
        }
    }
    __syncthreads();

    // --- quantum matvec on HMMA: psi[256][64] = a @ U (re + im) ---
    if (wid < 16) {
        const uint32_t abase = smem_base + OFF_AHI;
        const uint32_t ubf   = smem_base + OFF_UBF;
        const int prow = (wid << 4) + l15;
        uint32_t ahf[4][4], alf[4][4];
        #pragma unroll
        for (int ks = 0; ks < 4; ks++) {
            uint32_t kca = (uint32_t)(ks * 2) + (uint32_t)(lane >> 4);
            uint32_t ad = abase + (prow << 7) + ((kca ^ (uint32_t)(l15 & 7)) << 4);
            LDSM4(ahf[ks], ad);
            LDSM4(alf[ks], ad + 32768);
        }
        const int bl2 = lane & 7;
        const int bsel = (lane >> 3) & 1;
        const float s3 = (lane & 2) ? -1.f : 1.f;
        const float s4 = (lane & 1) ? -1.f : 1.f;
        float eacc[2][6];
        #pragma unroll
        for (int r2 = 0; r2 < 2; r2++)
            #pragma unroll
            for (int i = 0; i < 6; i++) eacc[r2][i] = 0.f;

        #pragma unroll
        for (int hf = 0; hf < 2; hf++) {
            float ar[4][4], ai[4][4];
            #pragma unroll
            for (int nt = 0; nt < 4; nt++)
                #pragma unroll
                for (int j = 0; j < 4; j++) { ar[nt][j] = 0.f; ai[nt][j] = 0.f; }
            #pragma unroll
            for (int nt = 0; nt < 4; nt++) {
                const int z0 = hf * 32 + nt * 8;
                const uint32_t brow2 = ubf + (uint32_t)((z0 + bl2) << 7);
                #pragma unroll
                for (int ks = 0; ks < 4; ks++) {
                    uint32_t bh[2], blo[2];
                    uint32_t ba = brow2 + ((((uint32_t)(ks * 2 + bsel)) ^ (uint32_t)bl2) << 4);
                    LDSM2(bh, ba);                 // Ur hi
                    LDSM2(blo, ba + 8192);         // Ur lo
                    MMA(ar[nt], ahf[ks], bh);
                    MMA(ar[nt], ahf[ks], blo);
                    MMA(ar[nt], alf[ks], bh);
                    LDSM2(bh, ba + 16384);         // Ui hi
                    LDSM2(blo, ba + 24576);        // Ui lo
                    MMA(ai[nt], ahf[ks], bh);
                    MMA(ai[nt], ahf[ks], blo);
                    MMA(ai[nt], alf[ks], bh);
                }
            }
            // expvals from fragments: z = hf*32 + nt*8 + (lane&3)*2 + j
            #pragma unroll
            for (int nt = 0; nt < 4; nt++) {
                #pragma unroll
                for (int r2 = 0; r2 < 2; r2++) {
                    #pragma unroll
                    for (int j = 0; j < 2; j++) {
                        float rr = ar[nt][r2 * 2 + j], ii = ai[nt][r2 * 2 + j];
                        float p = rr * rr + ii * ii;
                        eacc[r2][0] += hf ? -p : p;
                        eacc[r2][1] += (nt & 2) ? -p : p;
                        eacc[r2][2] += (nt & 1) ? -p : p;
                        eacc[r2][3] = fmaf(s3, p, eacc[r2][3]);
                        eacc[r2][4] = fmaf(s4, p, eacc[r2][4]);
                        eacc[r2][5] += j ? -p : p;
                    }
                }
            }
        }
        #pragma unroll
        for (int r2 = 0; r2 < 2; r2++)
            #pragma unroll
            for (int i = 0; i < 6; i++) {
                eacc[r2][i] += __shfl_xor_sync(0xffffffffu, eacc[r2][i], 1);
                eacc[r2][i] += __shfl_xor_sync(0xffffffffu, eacc[r2][i], 2);
            }
        if ((lane & 3) == 0) {
            int p0r = (wid << 4) + (lane >> 2);
            #pragma unroll
            for (int i = 0; i < 6; i++) {
                e_s[p0r * 9 + i] = eacc[0][i];
                e_s[(p0r + 8) * 9 + i] = eacc[1][i];
            }
        }
    }
    __syncthreads();

    // --- Epilogue: 512 threads = (pixel, 8-ch group), 4 rows ---
    if (tid < 512) {
        const int wE  = tid & 63;
        const int cgE = tid >> 6;
        #pragma unroll
        for (int o2 = 0; o2 < 4; o2++) {
            float ev[6];
            #pragma unroll
            for (int i = 0; i < 6; i++) ev[i] = e_s[(o2 * 64 + wE) * 9 + i];
            #pragma unroll
            for (int j = 0; j < 8; j++) {
                int c = cgE * 8 + j;
                float v = conv_s[(o2 * 64 + wE) * 80 + c] + pob[c] + prb[c];
                #pragma unroll
                for (int i = 0; i < 6; i++) v += pw[c * 6 + i] * ev[i];
                out[((b * 64 + c) * 64 + (h0 + o2)) * 64 + wE] = v;
            }
        }
    }
}

// ---------------------------------------------------------------------------
extern "C" void kernel_launch(void* const* d_in, const int* in_sizes, int n_in,
                              void* d_out, int out_size)
{
    (void)in_sizes; (void)n_in; (void)out_size;
    const float* x      = (const float*)d_in[0];
    const float* style  = (const float*)d_in[1];
    const float* dat_w  = (const float*)d_in[2];
    const float* dat_b  = (const float*)d_in[3];
    const float* s2d_w  = (const float*)d_in[4];
    const float* s2d_b  = (const float*)d_in[5];
    const float* qcnn   = (const float*)d_in[6];
    const float* meas   = (const float*)d_in[7];
    const float* out_w  = (const float*)d_in[8];
    const float* out_b  = (const float*)d_in[9];
    const float* res_w  = (const float*)d_in[10];
    const float* res_b  = (const float*)d_in[11];
    float* out = (float*)d_out;

    cudaFuncSetAttribute(qcnn_main_kernel,
                         cudaFuncAttributeMaxDynamicSharedMemorySize, SMEM_BYTES);

    qcnn_setup_b<<<180, 256>>>(res_w, dat_w);
    qcnn_setup_qc<<<1, 256>>>(style, s2d_w, s2d_b, qcnn, meas);
    qcnn_main_kernel<<<128, 640, SMEM_BYTES>>>(x, dat_b, out_w, out_b, res_b, out);
}

// round 10
// speedup vs baseline: 3.5231x; 1.1028x over previous
#include <cuda_runtime.h>
#include <cuda_bf16.h>
#include <math.h>
#include <stdint.h>

#define PI_F 3.14159265358979323846f
// B=8, C=64, H=W=64, K=3, PD=576, SD=128, NQ=6, NL=2

__device__ float g_style[48];
// Pre-swizzled B tiles: [9 shifts][hi 80x64 | lo 80x64] bf16, [n][k] rows,
// 16B chunk index ^= (n&7). 20480 B per shift.
__device__ __align__(16) unsigned short g_Bt[9][10240];
// U bf16 planes: [z][s] rows of 64 bf16 (128B), chunk ^= (z&7).
// plane 0 = Ur hi, 1 = Ur lo, 2 = Ui hi, 3 = Ui lo.
__device__ __align__(16) unsigned short g_Ubf[4][4096];

__device__ __forceinline__ uint32_t smem_u32(const void* p) {
    uint32_t a;
    asm("{ .reg .u64 t; cvta.to.shared.u64 t, %1; cvt.u32.u64 %0, t; }" : "=r"(a) : "l"(p));
    return a;
}

#define LDSM4(r, a) asm volatile("ldmatrix.sync.aligned.m8n8.x4.shared.b16 {%0,%1,%2,%3}, [%4];" \
    : "=r"((r)[0]), "=r"((r)[1]), "=r"((r)[2]), "=r"((r)[3]) : "r"(a))
#define LDSM2(r, a) asm volatile("ldmatrix.sync.aligned.m8n8.x2.shared.b16 {%0,%1}, [%2];" \
    : "=r"((r)[0]), "=r"((r)[1]) : "r"(a))
#define MMA(d, a, bb2) asm volatile( \
    "mma.sync.aligned.m16n8k16.row.col.f32.bf16.bf16.f32 " \
    "{%0,%1,%2,%3}, {%4,%5,%6,%7}, {%8,%9}, {%0,%1,%2,%3};" \
    : "+f"((d)[0]), "+f"((d)[1]), "+f"((d)[2]), "+f"((d)[3]) \
    : "r"((a)[0]), "r"((a)[1]), "r"((a)[2]), "r"((a)[3]), "r"((bb2)[0]), "r"((bb2)[1]))

__device__ __forceinline__ uint32_t pack_bf2(float a0, float a1) {
    __nv_bfloat16 h0 = __float2bfloat16(a0);
    __nv_bfloat16 h1 = __float2bfloat16(a1);
    return ((uint32_t)__bfloat16_as_ushort(h1) << 16) | __bfloat16_as_ushort(h0);
}

// ---------------------------------------------------------------------------
// Merged setup kernel: blocks 0..179 build B tiles; block 180 runs the
// quantum circuit (style angles + U bf16 planes).
// ---------------------------------------------------------------------------
__global__ void qcnn_setup_kernel(const float* __restrict__ style,
                                  const float* __restrict__ s2d_w,
                                  const float* __restrict__ s2d_b,
                                  const float* __restrict__ qcnn,
                                  const float* __restrict__ meas,
                                  const float* __restrict__ res_w,
                                  const float* __restrict__ dat_w)
{
    const int tid = threadIdx.x;  // 0..255

    if (blockIdx.x < 180) {
        int idx = blockIdx.x * 256 + tid;
        if (idx >= 46080) return;
        int shift = idx / 5120;
        int rem = idx - shift * 5120;
        int n = rem >> 6, c = rem & 63;
        int dy = shift / 3, dx = shift - dy * 3;
        int k = c * 9 + dy * 3 + dx;
        float wv = 0.f;
        if (n < 64) wv = res_w[n * 576 + k];
        else if (n < 70) wv = dat_w[(n - 64) * 576 + k];
        __nv_bfloat16 hi = __float2bfloat16(wv);
        __nv_bfloat16 lo = __float2bfloat16(wv - __bfloat162float(hi));
        int us = (n << 6) + (((c >> 3) ^ (n & 7)) << 3) + (c & 7);
        ((__nv_bfloat16*)g_Bt[shift])[us] = hi;
        ((__nv_bfloat16*)g_Bt[shift])[us + 5120] = lo;
        return;
    }

    // ---- block 180: quantum circuit ----
    if (tid < 48) {
        int b = tid / 6, j = tid - 6 * b;
        float acc = s2d_b[j];
        const float* sp = style + b * 128;
        const float* wp = s2d_w + j * 128;
        #pragma unroll 8
        for (int k = 0; k < 128; k++) acc += sp[k] * wp[k];
        g_style[tid] = tanhf(acc) * PI_F;
    }

    const int c = tid >> 2;
    const int q = tid & 3;
    const unsigned FULL = 0xffffffffu;
    float ur[16], ui[16];
    #pragma unroll
    for (int zz = 0; zz < 16; zz++) { ur[zz] = (c == q * 16 + zz) ? 1.f : 0.f; ui[zz] = 0.f; }

    for (int l = 0; l < 2; l++) {
        #pragma unroll
        for (int i = 0; i < 6; i++) {
            const int m = 1 << (5 - i);
            float thy = qcnn[((l * 6 + i) * 2 + 0) * 3 + 0];
            float thz = qcnn[((l * 6 + i) * 2 + 1) * 3 + 0];
            float cy, sy; sincosf(0.5f * thy, &sy, &cy);
            if (m < 16) {
                #pragma unroll
                for (int zz = 0; zz < 16; zz++) {
                    if (!(zz & m)) {
                        int z1 = zz | m;
                        float r0 = ur[zz], i0 = ui[zz], r1 = ur[z1], i1 = ui[z1];
                        ur[zz] = cy * r0 - sy * r1;  ui[zz] = cy * i0 - sy * i1;
                        ur[z1] = sy * r0 + cy * r1;  ui[z1] = sy * i0 + cy * i1;
                    }
                }
            } else {
                const int lane = m >> 4;
                const int bitv = (q * 16 & m) ? 1 : 0;
                #pragma unroll
                for (int zz = 0; zz < 16; zz++) {
                    float pr = __shfl_xor_sync(FULL, ur[zz], lane);
                    float pi = __shfl_xor_sync(FULL, ui[zz], lane);
                    if (bitv == 0) { ur[zz] = cy * ur[zz] - sy * pr; ui[zz] = cy * ui[zz] - sy * pi; }
                    else           { ur[zz] = sy * pr + cy * ur[zz]; ui[zz] = sy * pi + cy * ui[zz]; }
                }
            }
            float cz, sz; sincosf(0.5f * thz, &sz, &cz);
            #pragma unroll
            for (int zz = 0; zz < 16; zz++) {
                int z = q * 16 + zz;
                float ph = (z & m) ? sz : -sz;
                float r = ur[zz], im = ui[zz];
                ur[zz] = cz * r - ph * im;
                ui[zz] = cz * im + ph * r;
            }
        }
        #pragma unroll
        for (int i = 0; i < 6; i++) {
            const int mc = 1 << (5 - i);
            const int mt = 1 << (5 - ((i + 1) % 6));
            if (mt < 16) {
                #pragma unroll
                for (int zz = 0; zz < 16; zz++) {
                    int z = q * 16 + zz;
                    if ((z & mc) && !(zz & mt)) {
                        int z2 = zz | mt;
                        float tr = ur[zz], ti = ui[zz];
                        ur[zz] = ur[z2];  ui[zz] = ui[z2];
                        ur[z2] = tr;      ui[z2] = ti;
                    }
                }
            } else {
                const int lane = mt >> 4;
                #pragma unroll
                for (int zz = 0; zz < 16; zz++) {
                    float pr = __shfl_xor_sync(FULL, ur[zz], lane);
                    float pi = __shfl_xor_sync(FULL, ui[zz], lane);
                    int z = q * 16 + zz;
                    if (z & mc) { ur[zz] = pr; ui[zz] = pi; }
                }
            }
        }
    }
    #pragma unroll
    for (int i = 0; i < 6; i++) {
        const int m = 1 << (5 - i);
        float th = meas[i * 3 + 0], ph = meas[i * 3 + 1], la = meas[i * 3 + 2];
        float ct, st; sincosf(0.5f * th, &st, &ct);
        float cl, sl; sincosf(la, &sl, &cl);
        float cp, sp; sincosf(ph, &sp, &cp);
        float cpl, spl; sincosf(ph + la, &spl, &cpl);
        float u01r = -cl * st, u01i = -sl * st;
        float u10r =  cp * st, u10i =  sp * st;
        float u11r = cpl * ct, u11i = spl * ct;
        if (m < 16) {
            #pragma unroll
            for (int zz = 0; zz < 16; zz++) {
                if (!(zz & m)) {
                    int z1 = zz | m;
                    float r0 = ur[zz], i0 = ui[zz], r1 = ur[z1], i1 = ui[z1];
                    ur[zz] = ct * r0 + u01r * r1 - u01i * i1;
                    ui[zz] = ct * i0 + u01r * i1 + u01i * r1;
                    ur[z1] = u10r * r0 - u10i * i0 + u11r * r1 - u11i * i1;
                    ui[z1] = u10r * i0 + u10i * r0 + u11r * i1 + u11i * r1;
                }
            }
        } else {
            const int lane = m >> 4;
            const int bitv = (q * 16 & m) ? 1 : 0;
            #pragma unroll
            for (int zz = 0; zz < 16; zz++) {
                float pr = __shfl_xor_sync(FULL, ur[zz], lane);
                float pi = __shfl_xor_sync(FULL, ui[zz], lane);
                float r0 = ur[zz], i0 = ui[zz];
                if (bitv == 0) {
                    ur[zz] = ct * r0 + u01r * pr - u01i * pi;
                    ui[zz] = ct * i0 + u01r * pi + u01i * pr;
                } else {
                    ur[zz] = u10r * pr - u10i * pi + u11r * r0 - u11i * i0;
                    ui[zz] = u10r * pi + u10i * pr + u11r * i0 + u11i * r0;
                }
            }
        }
    }
    // bf16 split planes, transposed to [z][s], ldmatrix-swizzled
    #pragma unroll
    for (int zz = 0; zz < 16; zz++) {
        int z = q * 16 + zz;
        int us = (z << 6) + (((c >> 3) ^ (z & 7)) << 3) + (c & 7);
        __nv_bfloat16 rh = __float2bfloat16(ur[zz]);
        __nv_bfloat16 rl = __float2bfloat16(ur[zz] - __bfloat162float(rh));
        __nv_bfloat16 ih = __float2bfloat16(ui[zz]);
        __nv_bfloat16 il = __float2bfloat16(ui[zz] - __bfloat162float(ih));
        ((__nv_bfloat16*)g_Ubf[0])[us] = rh;
        ((__nv_bfloat16*)g_Ubf[1])[us] = rl;
        ((__nv_bfloat16*)g_Ubf[2])[us] = ih;
        ((__nv_bfloat16*)g_Ubf[3])[us] = il;
    }
}

// ---------------------------------------------------------------------------
// Main kernel: 128 blocks x 640 threads (single wave). Block = (b, 4 rows).
// Conv AND quantum matvec on mma.sync m16n8k16 bf16 (3-term split each).
// SMEM (bytes):
//   XPH@0(50688) XPL@50688 | B0@101376(20480) B1@121856(20480)
//   UBF@147456 (32768)  e_s@180224(9216)
//   pw@189440(1536) pob@190976(256) prb@191232(256) pst@191488(64)
// Overlays (post-conv): conv_s@0 [4][64][80]f32 (81920),
//   a_hi@81920(32768), a_lo@114688(32768)
// ---------------------------------------------------------------------------
#define OFF_XPL  50688
#define OFF_B0   101376
#define OFF_AHI  81920
#define OFF_ALO  114688
#define OFF_UBF  147456
#define OFF_ES   180224
#define OFF_PW   189440
#define OFF_POB  190976
#define OFF_PRB  191232
#define OFF_PST  191488
#define SMEM_BYTES 191552

__global__ __launch_bounds__(640, 1)
void qcnn_main_kernel(const float* __restrict__ x,
                      const float* __restrict__ dat_b,
                      const float* __restrict__ out_w,
                      const float* __restrict__ out_b,
                      const float* __restrict__ res_b,
                      float* __restrict__ out)
{
    extern __shared__ char smc[];
    const uint32_t smem_base = smem_u32(smc);
    float* conv_s = (float*)smc;                 // overlay post-GEMM
    float* e_s    = (float*)(smc + OFF_ES);
    float* pw     = (float*)(smc + OFF_PW);
    float* pob    = (float*)(smc + OFF_POB);
    float* prb    = (float*)(smc + OFF_PRB);
    float* pst    = (float*)(smc + OFF_PST);

    const int tid  = threadIdx.x;
    const int wid  = tid >> 5;
    const int lane = tid & 31;
    const int b    = blockIdx.x >> 4;
    const int h0   = (blockIdx.x & 15) << 2;

    // --- conflict-free transpose staging of input hi/lo planes ---
    // Task = (r, w-half, 8-channel chunk): lane = w within half.
    // 8 coalesced LDG.32 -> pack 16B per plane -> 1 STS.128 per plane
    // (wavefront groups cover 8 distinct swizzled chunks = 32 banks).
    for (int t = wid; t < 96; t += 20) {
        const int r  = t >> 4;
        const int wh = (t >> 3) & 1;
        const int ch = t & 7;
        const int w  = wh * 32 + lane;    // padded w index 0..63
        const int gw = w - 1;
        const int hr = h0 + r - 1;
        const bool ok = (hr >= 0) && (hr < 64) && (gw >= 0);
        float v[8];
        #pragma unroll
        for (int c2 = 0; c2 < 8; c2++) {
            int cc = ch * 8 + c2;
            v[c2] = ok ? x[(((b * 64 + cc) * 64 + hr) << 6) + gw] : 0.f;
        }
        uint4 hi4, lo4;
        uint32_t* hp = (uint32_t*)&hi4;
        uint32_t* lp = (uint32_t*)&lo4;
        #pragma unroll
        for (int j = 0; j < 4; j++) {
            float a0 = v[2 * j], a1 = v[2 * j + 1];
            __nv_bfloat16 h0b = __float2bfloat16(a0);
            __nv_bfloat16 h1b = __float2bfloat16(a1);
            hp[j] = ((uint32_t)__bfloat16_as_ushort(h1b) << 16) | __bfloat16_as_ushort(h0b);
            lp[j] = pack_bf2(a0 - __bfloat162float(h0b), a1 - __bfloat162float(h1b));
        }
        const int addr = ((r * 66 + w) << 7) + ((ch ^ (w & 7)) << 4);
        *(uint4*)(smc + addr) = hi4;
        *(uint4*)(smc + OFF_XPL + addr) = lo4;
    }
    // edge columns w=64 (gw=63) and w=65 (pad)
    if (tid < 96) {
        const int r  = tid >> 4;
        const int rem = tid & 15;
        const int ch = rem >> 1;
        const int w  = 64 + (rem & 1);
        const int hr = h0 + r - 1;
        const bool ok = (w == 64) && (hr >= 0) && (hr < 64);
        uint4 hi4, lo4;
        uint32_t* hp = (uint32_t*)&hi4;
        uint32_t* lp = (uint32_t*)&lo4;
        #pragma unroll
        for (int j = 0; j < 4; j++) {
            float a0 = 0.f, a1 = 0.f;
            if (ok) {
                int cc = ch * 8 + 2 * j;
                a0 = x[(((b * 64 + cc) * 64 + hr) << 6) + 63];
                a1 = x[(((b * 64 + cc + 1) * 64 + hr) << 6) + 63];
            }
            __nv_bfloat16 h0b = __float2bfloat16(a0);
            __nv_bfloat16 h1b = __float2bfloat16(a1);
            hp[j] = ((uint32_t)__bfloat16_as_ushort(h1b) << 16) | __bfloat16_as_ushort(h0b);
            lp[j] = pack_bf2(a0 - __bfloat162float(h0b), a1 - __bfloat162float(h1b));
        }
        const int addr = ((r * 66 + w) << 7) + ((ch ^ (w & 7)) << 4);
        *(uint4*)(smc + addr) = hi4;
        *(uint4*)(smc + OFF_XPL + addr) = lo4;
    }
    // --- B shift 0 into buf 0 ---
    {
        const uint4* src = (const uint4*)(g_Bt[0]);
        uint4* dst = (uint4*)(smc + OFF_B0);
        for (int i = tid; i < 1280; i += 640) dst[i] = src[i];
    }

    // compute-warp geometry (conv)
    const int mt  = wid >> 1;
    const int nh  = wid & 1;
    const int o   = mt >> 1;
    const int w0c = (mt & 1) * 32;
    const int n0  = nh * 40;
    const int l15 = lane & 15;
    const int bln = lane & 7;
    const uint32_t brow = (uint32_t)(n0 + bln) * 128;

    float acc[2][5][4];
    #pragma unroll
    for (int m = 0; m < 2; m++)
        #pragma unroll
        for (int nt = 0; nt < 5; nt++)
            #pragma unroll
            for (int j = 0; j < 4; j++) acc[m][nt][j] = 0.f;

    for (int st = 0; st < 9; st++) {
        __syncthreads();
        const uint32_t bb = smem_base + OFF_B0 + (uint32_t)(st & 1) * 20480;
        if (wid < 16) {
            const int dy = st / 3, dx = st - dy * 3;
            const int srow = o + dy;
            const int ws0 = w0c + l15 + dx;
            const int ws1 = ws0 + 16;
            const uint32_t arow0 = (uint32_t)((srow * 66 + ws0) << 7);
            const uint32_t arow1 = (uint32_t)((srow * 66 + ws1) << 7);
            const uint32_t sw0 = ws0 & 7, sw1 = ws1 & 7;
            const uint32_t xb = smem_base;
            #pragma unroll
            for (int k0 = 0; k0 < 64; k0 += 16) {
                const uint32_t kca = (uint32_t)(k0 >> 3) + (uint32_t)(lane >> 4);
                uint32_t ah0[4], ah1[4], al0[4], al1[4], bf[5][2];
                uint32_t ad0 = xb + arow0 + ((kca ^ sw0) << 4);
                uint32_t ad1 = xb + arow1 + ((kca ^ sw1) << 4);
                LDSM4(ah0, ad0);
                LDSM4(ah1, ad1);
                LDSM4(al0, ad0 + OFF_XPL);
                LDSM4(al1, ad1 + OFF_XPL);
                const uint32_t kcb = (uint32_t)(k0 >> 3) + (uint32_t)((lane >> 3) & 1);
                const uint32_t boff = bb + brow + ((kcb ^ (uint32_t)bln) << 4);
                #pragma unroll
                for (int nt = 0; nt < 5; nt++) LDSM2(bf[nt], boff + nt * 1024);
                #pragma unroll
                for (int nt = 0; nt < 5; nt++) { MMA(acc[0][nt], ah0, bf[nt]); MMA(acc[1][nt], ah1, bf[nt]); }
                #pragma unroll
                for (int nt = 0; nt < 5; nt++) { MMA(acc[0][nt], al0, bf[nt]); MMA(acc[1][nt], al1, bf[nt]); }
                #pragma unroll
                for (int nt = 0; nt < 5; nt++) LDSM2(bf[nt], boff + nt * 1024 + 10240);
                #pragma unroll
                for (int nt = 0; nt < 5; nt++) { MMA(acc[0][nt], ah0, bf[nt]); MMA(acc[1][nt], ah1, bf[nt]); }
            }
        } else {
            const int t2 = tid - 512;
            if (st < 8) {
                const uint4* src = (const uint4*)(g_Bt[st + 1]);
                uint4* dst = (uint4*)(smc + OFF_B0 + ((st + 1) & 1) * 20480);
                #pragma unroll
                for (int i = 0; i < 10; i++) dst[t2 + i * 128] = src[t2 + i * 128];
            }
            if (st == 0) {  // stage U planes + params
                for (int i = t2; i < 2048; i += 128)
                    ((uint4*)(smc + OFF_UBF))[i] = ((const uint4*)g_Ubf)[i];
                if (t2 < 96) ((uint4*)pw)[t2] = ((const uint4*)out_w)[t2];
                else if (t2 < 112) ((uint4*)pob)[t2 - 96] = ((const uint4*)out_b)[t2 - 96];
                else if (t2 < 128) ((uint4*)prb)[t2 - 112] = ((const uint4*)res_b)[t2 - 112];
                if (t2 < 6) { pst[t2] = g_style[b * 6 + t2]; pst[8 + t2] = dat_b[t2]; }
            }
        }
    }
    __syncthreads();   // all XP/B readers done -> safe to overlay conv_s

    // --- writeout conv acc -> conv_s [o][w][80] ---
    if (wid < 16) {
        const int r0 = lane >> 2;
        const int nc = n0 + (lane & 3) * 2;
        #pragma unroll
        for (int m = 0; m < 2; m++) {
            const int wpx = w0c + m * 16 + r0;
            #pragma unroll
            for (int nt = 0; nt < 5; nt++) {
                *(float2*)&conv_s[(o * 64 + wpx) * 80 + nc + nt * 8] =
                    make_float2(acc[m][nt][0], acc[m][nt][1]);
                *(float2*)&conv_s[(o * 64 + wpx + 8) * 80 + nc + nt * 8] =
                    make_float2(acc[m][nt][2], acc[m][nt][3]);
            }
        }
    }
    __syncthreads();

    // --- build product-state a as bf16 hi/lo planes [p(256)][s(64)] ---
    if (tid < 512) {
        const int q  = tid & 3;
        const int p2 = tid >> 2;
        #pragma unroll
        for (int it = 0; it < 2; it++) {
            const int p  = it * 128 + p2;
            const int o2 = p >> 6;
            const int wq = p & 63;
            float cc6[6], sn6[6];
            #pragma unroll
            for (int i = 0; i < 6; i++) {
                float pre = conv_s[(o2 * 64 + wq) * 80 + 64 + i];
                float th = tanhf(pre + pst[8 + i]) * PI_F + pst[i];
                sincosf(0.5f * th, &sn6[i], &cc6[i]);
            }
            char* ah = smc + OFF_AHI + (p << 7);
            char* al = smc + OFF_ALO + (p << 7);
            const int psw = p & 7;
            #pragma unroll
            for (int zz = 0; zz < 16; zz += 2) {
                int s = q * 16 + zz;
                float a0 = ((s >> 5) & 1) ? sn6[0] : cc6[0];
                float a1 = (((s + 1) >> 5) & 1) ? sn6[0] : cc6[0];
                #pragma unroll
                for (int i = 1; i < 6; i++) {
                    a0 *= ((s >> (5 - i)) & 1) ? sn6[i] : cc6[i];
                    a1 *= (((s + 1) >> (5 - i)) & 1) ? sn6[i] : cc6[i];
                }
                __nv_bfloat16 h0 = __float2bfloat16(a0);
                __nv_bfloat16 h1 = __float2bfloat16(a1);
                uint32_t vh = ((uint32_t)__bfloat16_as_ushort(h1) << 16) | __bfloat16_as_ushort(h0);
                uint32_t vl = pack_bf2(a0 - __bfloat162float(h0), a1 - __bfloat162float(h1));
                int off = ((((s >> 3)) ^ psw) << 4) + ((s & 7) << 1);
                *(uint32_t*)(ah + off) = vh;
                *(uint32_t*)(al + off) = vl;
            }
        }
    }
    __syncthreads();

    // --- quantum matvec on HMMA: psi[256][64] = a @ U (re + im) ---
    if (wid < 16) {
        const uint32_t abase = smem_base + OFF_AHI;
        const uint32_t ubf   = smem_base + OFF_UBF;
        const int prow = (wid << 4) + l15;
        uint32_t ahf[4][4], alf[4][4];
        #pragma unroll
        for (int ks = 0; ks < 4; ks++) {
            uint32_t kca = (uint32_t)(ks * 2) + (uint32_t)(lane >> 4);
            uint32_t ad = abase + (prow << 7) + ((kca ^ (uint32_t)(l15 & 7)) << 4);
            LDSM4(ahf[ks], ad);
            LDSM4(alf[ks], ad + 32768);
        }
        const int bl2 = lane & 7;
        const int bsel = (lane >> 3) & 1;
        const float s3 = (lane & 2) ? -1.f : 1.f;
        const float s4 = (lane & 1) ? -1.f : 1.f;
        float eacc[2][6];
        #pragma unroll
        for (int r2 = 0; r2 < 2; r2++)
            #pragma unroll
            for (int i = 0; i < 6; i++) eacc[r2][i] = 0.f;

        #pragma unroll
        for (int hf = 0; hf < 2; hf++) {
            float ar[4][4], ai[4][4];
            #pragma unroll
            for (int nt = 0; nt < 4; nt++)
                #pragma unroll
                for (int j = 0; j < 4; j++) { ar[nt][j] = 0.f; ai[nt][j] = 0.f; }
            #pragma unroll
            for (int nt = 0; nt < 4; nt++) {
                const int z0 = hf * 32 + nt * 8;
                const uint32_t brow2 = ubf + (uint32_t)((z0 + bl2) << 7);
                #pragma unroll
                for (int ks = 0; ks < 4; ks++) {
                    uint32_t bh[2], blo[2];
                    uint32_t ba = brow2 + ((((uint32_t)(ks * 2 + bsel)) ^ (uint32_t)bl2) << 4);
                    LDSM2(bh, ba);                 // Ur hi
                    LDSM2(blo, ba + 8192);         // Ur lo
                    MMA(ar[nt], ahf[ks], bh);
                    MMA(ar[nt], ahf[ks], blo);
                    MMA(ar[nt], alf[ks], bh);
                    LDSM2(bh, ba + 16384);         // Ui hi
                    LDSM2(blo, ba + 24576);        // Ui lo
                    MMA(ai[nt], ahf[ks], bh);
                    MMA(ai[nt], ahf[ks], blo);
                    MMA(ai[nt], alf[ks], bh);
                }
            }
            // expvals from fragments: z = hf*32 + nt*8 + (lane&3)*2 + j
            #pragma unroll
            for (int nt = 0; nt < 4; nt++) {
                #pragma unroll
                for (int r2 = 0; r2 < 2; r2++) {
                    #pragma unroll
                    for (int j = 0; j < 2; j++) {
                        float rr = ar[nt][r2 * 2 + j], ii = ai[nt][r2 * 2 + j];
                        float p = rr * rr + ii * ii;
                        eacc[r2][0] += hf ? -p : p;
                        eacc[r2][1] += (nt & 2) ? -p : p;
                        eacc[r2][2] += (nt & 1) ? -p : p;
                        eacc[r2][3] = fmaf(s3, p, eacc[r2][3]);
                        eacc[r2][4] = fmaf(s4, p, eacc[r2][4]);
                        eacc[r2][5] += j ? -p : p;
                    }
                }
            }
        }
        #pragma unroll
        for (int r2 = 0; r2 < 2; r2++)
            #pragma unroll
            for (int i = 0; i < 6; i++) {
                eacc[r2][i] += __shfl_xor_sync(0xffffffffu, eacc[r2][i], 1);
                eacc[r2][i] += __shfl_xor_sync(0xffffffffu, eacc[r2][i], 2);
            }
        if ((lane & 3) == 0) {
            int p0r = (wid << 4) + (lane >> 2);
            #pragma unroll
            for (int i = 0; i < 6; i++) {
                e_s[p0r * 9 + i] = eacc[0][i];
                e_s[(p0r + 8) * 9 + i] = eacc[1][i];
            }
        }
    }
    __syncthreads();

    // --- Epilogue: 512 threads = (pixel, 8-ch group), 4 rows ---
    if (tid < 512) {
        const int wE  = tid & 63;
        const int cgE = tid >> 6;
        #pragma unroll
        for (int o2 = 0; o2 < 4; o2++) {
            float ev[6];
            #pragma unroll
            for (int i = 0; i < 6; i++) ev[i] = e_s[(o2 * 64 + wE) * 9 + i];
            #pragma unroll
            for (int j = 0; j < 8; j++) {
                int c = cgE * 8 + j;
                float v = conv_s[(o2 * 64 + wE) * 80 + c] + pob[c] + prb[c];
                #pragma unroll
                for (int i = 0; i < 6; i++) v += pw[c * 6 + i] * ev[i];
                out[((b * 64 + c) * 64 + (h0 + o2)) * 64 + wE] = v;
            }
        }
    }
}

// ---------------------------------------------------------------------------
extern "C" void kernel_launch(void* const* d_in, const int* in_sizes, int n_in,
                              void* d_out, int out_size)
{
    (void)in_sizes; (void)n_in; (void)out_size;
    const float* x      = (const float*)d_in[0];
    const float* style  = (const float*)d_in[1];
    const float* dat_w  = (const float*)d_in[2];
    const float* dat_b  = (const float*)d_in[3];
    const float* s2d_w  = (const float*)d_in[4];
    const float* s2d_b  = (const float*)d_in[5];
    const float* qcnn   = (const float*)d_in[6];
    const float* meas   = (const float*)d_in[7];
    const float* out_w  = (const float*)d_in[8];
    const float* out_b  = (const float*)d_in[9];
    const float* res_w  = (const float*)d_in[10];
    const float* res_b  = (const float*)d_in[11];
    float* out = (float*)d_out;

    cudaFuncSetAttribute(qcnn_main_kernel,
                         cudaFuncAttributeMaxDynamicSharedMemorySize, SMEM_BYTES);

    qcnn_setup_kernel<<<181, 256>>>(style, s2d_w, s2d_b, qcnn, meas, res_w, dat_w);
    qcnn_main_kernel<<<128, 640, SMEM_BYTES>>>(x, dat_b, out_w, out_b, res_b, out);
}